// round 1
// baseline (speedup 1.0000x reference)
#include <cuda_runtime.h>
#include <cuda_bf16.h>
#include <math.h>

// Problem constants
#define BATCH 2
#define SEQ 2048
#define DMODEL 1024
#define NHEADS 16
#define DK 64
#define MROWS (BATCH * SEQ)      // 4096
#define HALF_DK 32               // rope pairs per head

// ---------------------------------------------------------------------------
// Scratch buffers (allocation-free rule: __device__ globals)
// ---------------------------------------------------------------------------
__device__ float g_Q[MROWS * DMODEL];
__device__ float g_K[MROWS * DMODEL];
__device__ float g_V[MROWS * DMODEL];
__device__ float g_O[MROWS * DMODEL];
__device__ float g_cos[SEQ * HALF_DK];
__device__ float g_sin[SEQ * HALF_DK];

// ---------------------------------------------------------------------------
// SGEMM NT: C[M,N] = A[M,K] * B[N,K]^T  (both row-major)
// 128x128 block, BK=8, 256 threads, 8x8 per-thread microtile.
// ---------------------------------------------------------------------------
__global__ __launch_bounds__(256) void sgemm_nt(
    const float* __restrict__ A, const float* __restrict__ B,
    float* __restrict__ C, int M, int N, int K)
{
    __shared__ float As[8][128];
    __shared__ float Bs[8][128];

    int tid = threadIdx.x;
    int bx = blockIdx.x;   // N tile
    int by = blockIdx.y;   // M tile

    const float* Ablk = A + (size_t)by * 128 * K;
    const float* Bblk = B + (size_t)bx * 128 * K;

    int lrow = tid >> 1;          // 0..127
    int lcol = (tid & 1) * 4;     // 0 or 4

    int tx = tid & 15;            // 0..15 (N micro)
    int ty = tid >> 4;            // 0..15 (M micro)

    float acc[8][8];
    #pragma unroll
    for (int i = 0; i < 8; i++)
        #pragma unroll
        for (int j = 0; j < 8; j++) acc[i][j] = 0.f;

    for (int k0 = 0; k0 < K; k0 += 8) {
        float4 av = *(const float4*)(Ablk + (size_t)lrow * K + k0 + lcol);
        float4 bv = *(const float4*)(Bblk + (size_t)lrow * K + k0 + lcol);
        As[lcol + 0][lrow] = av.x; As[lcol + 1][lrow] = av.y;
        As[lcol + 2][lrow] = av.z; As[lcol + 3][lrow] = av.w;
        Bs[lcol + 0][lrow] = bv.x; Bs[lcol + 1][lrow] = bv.y;
        Bs[lcol + 2][lrow] = bv.z; Bs[lcol + 3][lrow] = bv.w;
        __syncthreads();

        #pragma unroll
        for (int kk = 0; kk < 8; kk++) {
            float a[8], b[8];
            *(float4*)(a)     = *(const float4*)&As[kk][ty * 8];
            *(float4*)(a + 4) = *(const float4*)&As[kk][ty * 8 + 4];
            *(float4*)(b)     = *(const float4*)&Bs[kk][tx * 8];
            *(float4*)(b + 4) = *(const float4*)&Bs[kk][tx * 8 + 4];
            #pragma unroll
            for (int i = 0; i < 8; i++)
                #pragma unroll
                for (int j = 0; j < 8; j++)
                    acc[i][j] += a[i] * b[j];
        }
        __syncthreads();
    }

    #pragma unroll
    for (int i = 0; i < 8; i++) {
        int row = by * 128 + ty * 8 + i;
        float* cp = C + (size_t)row * N + bx * 128 + tx * 8;
        *(float4*)(cp)     = make_float4(acc[i][0], acc[i][1], acc[i][2], acc[i][3]);
        *(float4*)(cp + 4) = make_float4(acc[i][4], acc[i][5], acc[i][6], acc[i][7]);
    }
}

// ---------------------------------------------------------------------------
// RoPE cos/sin table: g_cos/g_sin[pos][i], i = pair index 0..31
// Matches ref: inv = theta^(-(2i)/64) computed then rounded to f32,
// argument = f32(pos) * f32(inv), rounded to f32; sincos in double for accuracy.
// ---------------------------------------------------------------------------
__global__ void rope_table_kernel()
{
    int idx = blockIdx.x * blockDim.x + threadIdx.x;   // 65536
    if (idx >= SEQ * HALF_DK) return;
    int pos = idx >> 5;
    int i = idx & 31;
    double inv_d = exp(-((double)(2 * i) / 64.0) * log(10000.0));
    float inv_f = (float)inv_d;
    float arg_f = (float)pos * inv_f;                  // matches f32 ref argument
    double sv, cv;
    sincos((double)arg_f, &sv, &cv);
    g_cos[idx] = (float)cv;
    g_sin[idx] = (float)sv;
}

// ---------------------------------------------------------------------------
// Apply RoPE in place to a [MROWS, DMODEL] tensor (heads of 64, interleaved pairs)
// ---------------------------------------------------------------------------
__global__ __launch_bounds__(256) void rope_apply_kernel(
    float* __restrict__ X, const int* __restrict__ tokpos)
{
    int idx = blockIdx.x * blockDim.x + threadIdx.x;   // MROWS * 512 pairs
    if (idx >= MROWS * (DMODEL / 2)) return;
    int row = idx >> 9;         // /512
    int cp = idx & 511;         // pair index in row: h*32 + i
    int i = cp & 31;
    int pos = tokpos[row];
    float c = g_cos[pos * HALF_DK + i];
    float s = g_sin[pos * HALF_DK + i];
    float2* p = (float2*)&X[(size_t)row * DMODEL + cp * 2];
    float2 v = *p;
    float xe = v.x, xo = v.y;
    v.x = xe * c - xo * s;
    v.y = xe * s + xo * c;
    *p = v;
}

// ---------------------------------------------------------------------------
// Causal flash attention, fp32. One thread per query row.
// Block: 128 threads = 128 q rows. KV tiles of 32 staged in smem.
// Q row + O accumulator in registers (64 + 64).
// grid: (SEQ/128, BATCH*NHEADS)
// ---------------------------------------------------------------------------
#define BQ 128
#define BKV 32

__global__ __launch_bounds__(128) void attn_kernel(
    const float* __restrict__ Q, const float* __restrict__ K,
    const float* __restrict__ V, float* __restrict__ O)
{
    __shared__ float Ksm[BKV][DK];
    __shared__ float Vsm[BKV][DK];
    __shared__ float Ssc[BQ][BKV + 1];    // padded: conflict-free per-row access

    int qt = blockIdx.x;
    int bh = blockIdx.y;
    int b = bh >> 4;
    int h = bh & 15;
    size_t base = ((size_t)b * SEQ) * DMODEL + (size_t)h * DK;

    int tid = threadIdx.x;
    int qrow = qt * BQ + tid;

    // Load this thread's q row into registers
    float q[DK];
    const float* qp = Q + base + (size_t)qrow * DMODEL;
    #pragma unroll
    for (int d4 = 0; d4 < 16; d4++) {
        float4 v = *(const float4*)(qp + d4 * 4);
        q[4 * d4 + 0] = v.x; q[4 * d4 + 1] = v.y;
        q[4 * d4 + 2] = v.z; q[4 * d4 + 3] = v.w;
    }

    float o[DK];
    #pragma unroll
    for (int d = 0; d < DK; d++) o[d] = 0.f;
    float m = -INFINITY;
    float l = 0.f;

    int ntiles = (qt * BQ + BQ) / BKV;    // causal bound for this q tile

    for (int t = 0; t < ntiles; t++) {
        // ---- stage K/V tile (all threads) ----
        const float* kp = K + base + (size_t)(t * BKV) * DMODEL;
        const float* vp = V + base + (size_t)(t * BKV) * DMODEL;
        #pragma unroll
        for (int i = 0; i < 4; i++) {
            int idx = i * 128 + tid;       // 512 float4 chunks
            int r = idx >> 4;
            int c = (idx & 15) * 4;
            *(float4*)&Ksm[r][c] = *(const float4*)(kp + (size_t)r * DMODEL + c);
            *(float4*)&Vsm[r][c] = *(const float4*)(vp + (size_t)r * DMODEL + c);
        }
        __syncthreads();

        int kbase = t * BKV;
        if (kbase <= qrow) {               // row has at least one unmasked col
            // ---- scores + row max ----
            float mloc = m;
            #pragma unroll 4
            for (int j = 0; j < BKV; j++) {
                float s = 0.f;
                #pragma unroll
                for (int d4 = 0; d4 < 16; d4++) {
                    float4 kk = *(const float4*)&Ksm[j][d4 * 4];
                    s += q[4 * d4 + 0] * kk.x + q[4 * d4 + 1] * kk.y
                       + q[4 * d4 + 2] * kk.z + q[4 * d4 + 3] * kk.w;
                }
                s *= 0.125f;               // 1/sqrt(64)
                if (kbase + j > qrow) s = -INFINITY;
                Ssc[tid][j] = s;
                mloc = fmaxf(mloc, s);
            }

            // ---- online softmax update ----
            float corr = __expf(m - mloc);     // exp(-inf)=0 on first tile
            float lsum = 0.f;
            #pragma unroll
            for (int j = 0; j < BKV; j++) {
                float p = __expf(Ssc[tid][j] - mloc);
                Ssc[tid][j] = p;
                lsum += p;
            }
            l = l * corr + lsum;
            #pragma unroll
            for (int d = 0; d < DK; d++) o[d] *= corr;

            // ---- accumulate P*V ----
            #pragma unroll 2
            for (int j = 0; j < BKV; j++) {
                float p = Ssc[tid][j];
                #pragma unroll
                for (int d4 = 0; d4 < 16; d4++) {
                    float4 vv = *(const float4*)&Vsm[j][d4 * 4];
                    o[4 * d4 + 0] += p * vv.x;
                    o[4 * d4 + 1] += p * vv.y;
                    o[4 * d4 + 2] += p * vv.z;
                    o[4 * d4 + 3] += p * vv.w;
                }
            }
            m = mloc;
        }
        __syncthreads();
    }

    float inv_l = 1.f / l;
    float* op = O + base + (size_t)qrow * DMODEL;
    #pragma unroll
    for (int d4 = 0; d4 < 16; d4++) {
        float4 v;
        v.x = o[4 * d4 + 0] * inv_l;
        v.y = o[4 * d4 + 1] * inv_l;
        v.z = o[4 * d4 + 2] * inv_l;
        v.w = o[4 * d4 + 3] * inv_l;
        *(float4*)(op + d4 * 4) = v;
    }
}

// ---------------------------------------------------------------------------
// Launch
// ---------------------------------------------------------------------------
extern "C" void kernel_launch(void* const* d_in, const int* in_sizes, int n_in,
                              void* d_out, int out_size)
{
    const float* x  = (const float*)d_in[0];
    const float* Wq = (const float*)d_in[1];
    const float* Wk = (const float*)d_in[2];
    const float* Wv = (const float*)d_in[3];
    const float* Wo = (const float*)d_in[4];
    const int* tokpos = (const int*)d_in[5];
    float* out = (float*)d_out;

    float *Qp, *Kp, *Vp, *Op;
    cudaGetSymbolAddress((void**)&Qp, g_Q);
    cudaGetSymbolAddress((void**)&Kp, g_K);
    cudaGetSymbolAddress((void**)&Vp, g_V);
    cudaGetSymbolAddress((void**)&Op, g_O);

    dim3 gemm_grid(DMODEL / 128, MROWS / 128);   // (8, 32)
    dim3 gemm_block(256);

    // QKV projections
    sgemm_nt<<<gemm_grid, gemm_block>>>(x, Wq, Qp, MROWS, DMODEL, DMODEL);
    sgemm_nt<<<gemm_grid, gemm_block>>>(x, Wk, Kp, MROWS, DMODEL, DMODEL);
    sgemm_nt<<<gemm_grid, gemm_block>>>(x, Wv, Vp, MROWS, DMODEL, DMODEL);

    // RoPE
    rope_table_kernel<<<(SEQ * HALF_DK + 255) / 256, 256>>>();
    int npairs = MROWS * (DMODEL / 2);
    rope_apply_kernel<<<(npairs + 255) / 256, 256>>>(Qp, tokpos);
    rope_apply_kernel<<<(npairs + 255) / 256, 256>>>(Kp, tokpos);

    // Attention
    dim3 attn_grid(SEQ / BQ, BATCH * NHEADS);    // (16, 32)
    attn_kernel<<<attn_grid, 128>>>(Qp, Kp, Vp, Op);

    // Output projection
    sgemm_nt<<<gemm_grid, gemm_block>>>(Op, Wo, out, MROWS, DMODEL, DMODEL);
}

// round 2
// speedup vs baseline: 1.5393x; 1.5393x over previous
#include <cuda_runtime.h>
#include <cuda_bf16.h>
#include <math.h>

// Problem constants
#define BATCH 2
#define SEQ 2048
#define DMODEL 1024
#define NHEADS 16
#define DK 64
#define MROWS (BATCH * SEQ)      // 4096
#define HALF_DK 32               // rope pairs per head

// ---------------------------------------------------------------------------
// Scratch buffers (allocation-free rule: __device__ globals)
// ---------------------------------------------------------------------------
__device__ float g_Q[MROWS * DMODEL];
__device__ float g_K[MROWS * DMODEL];
__device__ float g_V[MROWS * DMODEL];
__device__ float g_O[MROWS * DMODEL];
__device__ float g_cos[SEQ * HALF_DK];
__device__ float g_sin[SEQ * HALF_DK];

// ---------------------------------------------------------------------------
// tf32 helpers
// ---------------------------------------------------------------------------
__device__ __forceinline__ unsigned f2tf32(float f) {
    unsigned u;
    asm("cvt.rna.tf32.f32 %0, %1;" : "=r"(u) : "f"(f));
    return u;
}

__device__ __forceinline__ void mma_tf32(
    float& c0, float& c1, float& c2, float& c3,
    unsigned a0, unsigned a1, unsigned a2, unsigned a3,
    unsigned b0, unsigned b1)
{
    asm volatile(
        "mma.sync.aligned.m16n8k8.row.col.f32.tf32.tf32.f32 "
        "{%0,%1,%2,%3}, {%4,%5,%6,%7}, {%8,%9}, {%0,%1,%2,%3};"
        : "+f"(c0), "+f"(c1), "+f"(c2), "+f"(c3)
        : "r"(a0), "r"(a1), "r"(a2), "r"(a3), "r"(b0), "r"(b1));
}

// ---------------------------------------------------------------------------
// tf32 GEMM NT: C[M,N] = A[M,K] * B[N,K]^T  (both row-major)
// 128x128 block tile, BK=32, 256 threads (8 warps), warp tile 64x32.
// mma.sync m16n8k8 tf32. Smem rows padded to 36 floats -> conflict-free
// fragment LDS (bank = lane).
// gridDim.z selects among up to 3 (B, C) pairs for fused QKV.
// ---------------------------------------------------------------------------
#define GBM 128
#define GBN 128
#define GBK 32
#define GPAD 36

__global__ __launch_bounds__(256) void gemm_tf32_nt(
    const float* __restrict__ A,
    const float* __restrict__ B0, float* __restrict__ C0,
    const float* __restrict__ B1, float* __restrict__ C1,
    const float* __restrict__ B2, float* __restrict__ C2,
    int M, int N, int K)
{
    __shared__ unsigned As[GBM * GPAD];
    __shared__ unsigned Bs[GBN * GPAD];

    const float* B = B0; float* C = C0;
    if (blockIdx.z == 1) { B = B1; C = C1; }
    else if (blockIdx.z == 2) { B = B2; C = C2; }

    int tid = threadIdx.x;
    int warp = tid >> 5;
    int lane = tid & 31;
    int grp = lane >> 2;        // 0..7
    int tig = lane & 3;         // 0..3

    int wm = warp & 1;          // warp row (64 M-rows each)
    int wn = warp >> 1;         // warp col (32 N-cols each)

    int bx = blockIdx.x;        // N tile
    int by = blockIdx.y;        // M tile

    const float* Ablk = A + (size_t)by * GBM * K;
    const float* Bblk = B + (size_t)bx * GBN * K;

    // global load mapping: thread -> (row = tid/8 + i*32, col4 = (tid%8)*4)
    int lr = tid >> 3;
    int lc = (tid & 7) * 4;

    float acc[4][4][4];
    #pragma unroll
    for (int i = 0; i < 4; i++)
        #pragma unroll
        for (int j = 0; j < 4; j++)
            #pragma unroll
            for (int f = 0; f < 4; f++) acc[i][j][f] = 0.f;

    for (int k0 = 0; k0 < K; k0 += GBK) {
        // ---- stage + convert to tf32 ----
        #pragma unroll
        for (int i = 0; i < 4; i++) {
            int row = lr + i * 32;
            float4 av = *(const float4*)(Ablk + (size_t)row * K + k0 + lc);
            float4 bv = *(const float4*)(Bblk + (size_t)row * K + k0 + lc);
            unsigned* ap = &As[row * GPAD + lc];
            unsigned* bp = &Bs[row * GPAD + lc];
            ap[0] = f2tf32(av.x); ap[1] = f2tf32(av.y);
            ap[2] = f2tf32(av.z); ap[3] = f2tf32(av.w);
            bp[0] = f2tf32(bv.x); bp[1] = f2tf32(bv.y);
            bp[2] = f2tf32(bv.z); bp[3] = f2tf32(bv.w);
        }
        __syncthreads();

        #pragma unroll
        for (int ks = 0; ks < GBK / 8; ks++) {
            int kk = ks * 8 + tig;
            unsigned af[4][4];
            #pragma unroll
            for (int mi = 0; mi < 4; mi++) {
                int m = wm * 64 + mi * 16 + grp;
                af[mi][0] = As[m * GPAD + kk];
                af[mi][1] = As[(m + 8) * GPAD + kk];
                af[mi][2] = As[m * GPAD + kk + 4];
                af[mi][3] = As[(m + 8) * GPAD + kk + 4];
            }
            unsigned bf[4][2];
            #pragma unroll
            for (int nj = 0; nj < 4; nj++) {
                int n = wn * 32 + nj * 8 + grp;
                bf[nj][0] = Bs[n * GPAD + kk];
                bf[nj][1] = Bs[n * GPAD + kk + 4];
            }
            #pragma unroll
            for (int mi = 0; mi < 4; mi++)
                #pragma unroll
                for (int nj = 0; nj < 4; nj++)
                    mma_tf32(acc[mi][nj][0], acc[mi][nj][1],
                             acc[mi][nj][2], acc[mi][nj][3],
                             af[mi][0], af[mi][1], af[mi][2], af[mi][3],
                             bf[nj][0], bf[nj][1]);
        }
        __syncthreads();
    }

    // ---- epilogue ----
    #pragma unroll
    for (int mi = 0; mi < 4; mi++) {
        int row0 = by * GBM + wm * 64 + mi * 16 + grp;
        #pragma unroll
        for (int nj = 0; nj < 4; nj++) {
            int col = bx * GBN + wn * 32 + nj * 8 + tig * 2;
            *(float2*)&C[(size_t)row0 * N + col] =
                make_float2(acc[mi][nj][0], acc[mi][nj][1]);
            *(float2*)&C[(size_t)(row0 + 8) * N + col] =
                make_float2(acc[mi][nj][2], acc[mi][nj][3]);
        }
    }
}

// ---------------------------------------------------------------------------
// RoPE cos/sin table
// ---------------------------------------------------------------------------
__global__ void rope_table_kernel()
{
    int idx = blockIdx.x * blockDim.x + threadIdx.x;
    if (idx >= SEQ * HALF_DK) return;
    int pos = idx >> 5;
    int i = idx & 31;
    double inv_d = exp(-((double)(2 * i) / 64.0) * log(10000.0));
    float inv_f = (float)inv_d;
    float arg_f = (float)pos * inv_f;
    double sv, cv;
    sincos((double)arg_f, &sv, &cv);
    g_cos[idx] = (float)cv;
    g_sin[idx] = (float)sv;
}

// ---------------------------------------------------------------------------
// Apply RoPE in place to Q and K ([MROWS, DMODEL], heads of 64, interleaved)
// blockIdx.y selects tensor.
// ---------------------------------------------------------------------------
__global__ __launch_bounds__(256) void rope_apply_kernel(
    float* __restrict__ XQ, float* __restrict__ XK,
    const int* __restrict__ tokpos)
{
    int idx = blockIdx.x * blockDim.x + threadIdx.x;
    if (idx >= MROWS * (DMODEL / 2)) return;
    float* X = blockIdx.y ? XK : XQ;
    int row = idx >> 9;
    int cp = idx & 511;
    int i = cp & 31;
    int pos = tokpos[row];
    float c = g_cos[pos * HALF_DK + i];
    float s = g_sin[pos * HALF_DK + i];
    float2* p = (float2*)&X[(size_t)row * DMODEL + cp * 2];
    float2 v = *p;
    float xe = v.x, xo = v.y;
    v.x = xe * c - xo * s;
    v.y = xe * s + xo * c;
    *p = v;
}

// ---------------------------------------------------------------------------
// Causal flash attention, fp32 (unchanged this round).
// ---------------------------------------------------------------------------
#define BQ 128
#define BKV 32

__global__ __launch_bounds__(128) void attn_kernel(
    const float* __restrict__ Q, const float* __restrict__ K,
    const float* __restrict__ V, float* __restrict__ O)
{
    __shared__ float Ksm[BKV][DK];
    __shared__ float Vsm[BKV][DK];
    __shared__ float Ssc[BQ][BKV + 1];

    int qt = blockIdx.x;
    int bh = blockIdx.y;
    int b = bh >> 4;
    int h = bh & 15;
    size_t base = ((size_t)b * SEQ) * DMODEL + (size_t)h * DK;

    int tid = threadIdx.x;
    int qrow = qt * BQ + tid;

    float q[DK];
    const float* qp = Q + base + (size_t)qrow * DMODEL;
    #pragma unroll
    for (int d4 = 0; d4 < 16; d4++) {
        float4 v = *(const float4*)(qp + d4 * 4);
        q[4 * d4 + 0] = v.x; q[4 * d4 + 1] = v.y;
        q[4 * d4 + 2] = v.z; q[4 * d4 + 3] = v.w;
    }

    float o[DK];
    #pragma unroll
    for (int d = 0; d < DK; d++) o[d] = 0.f;
    float m = -INFINITY;
    float l = 0.f;

    int ntiles = (qt * BQ + BQ) / BKV;

    for (int t = 0; t < ntiles; t++) {
        const float* kp = K + base + (size_t)(t * BKV) * DMODEL;
        const float* vp = V + base + (size_t)(t * BKV) * DMODEL;
        #pragma unroll
        for (int i = 0; i < 4; i++) {
            int idx = i * 128 + tid;
            int r = idx >> 4;
            int c = (idx & 15) * 4;
            *(float4*)&Ksm[r][c] = *(const float4*)(kp + (size_t)r * DMODEL + c);
            *(float4*)&Vsm[r][c] = *(const float4*)(vp + (size_t)r * DMODEL + c);
        }
        __syncthreads();

        int kbase = t * BKV;
        if (kbase <= qrow) {
            float mloc = m;
            #pragma unroll 4
            for (int j = 0; j < BKV; j++) {
                float s = 0.f;
                #pragma unroll
                for (int d4 = 0; d4 < 16; d4++) {
                    float4 kk = *(const float4*)&Ksm[j][d4 * 4];
                    s += q[4 * d4 + 0] * kk.x + q[4 * d4 + 1] * kk.y
                       + q[4 * d4 + 2] * kk.z + q[4 * d4 + 3] * kk.w;
                }
                s *= 0.125f;
                if (kbase + j > qrow) s = -INFINITY;
                Ssc[tid][j] = s;
                mloc = fmaxf(mloc, s);
            }

            float corr = __expf(m - mloc);
            float lsum = 0.f;
            #pragma unroll
            for (int j = 0; j < BKV; j++) {
                float p = __expf(Ssc[tid][j] - mloc);
                Ssc[tid][j] = p;
                lsum += p;
            }
            l = l * corr + lsum;
            #pragma unroll
            for (int d = 0; d < DK; d++) o[d] *= corr;

            #pragma unroll 2
            for (int j = 0; j < BKV; j++) {
                float p = Ssc[tid][j];
                #pragma unroll
                for (int d4 = 0; d4 < 16; d4++) {
                    float4 vv = *(const float4*)&Vsm[j][d4 * 4];
                    o[4 * d4 + 0] += p * vv.x;
                    o[4 * d4 + 1] += p * vv.y;
                    o[4 * d4 + 2] += p * vv.z;
                    o[4 * d4 + 3] += p * vv.w;
                }
            }
            m = mloc;
        }
        __syncthreads();
    }

    float inv_l = 1.f / l;
    float* op = O + base + (size_t)qrow * DMODEL;
    #pragma unroll
    for (int d4 = 0; d4 < 16; d4++) {
        float4 v;
        v.x = o[4 * d4 + 0] * inv_l;
        v.y = o[4 * d4 + 1] * inv_l;
        v.z = o[4 * d4 + 2] * inv_l;
        v.w = o[4 * d4 + 3] * inv_l;
        *(float4*)(op + d4 * 4) = v;
    }
}

// ---------------------------------------------------------------------------
// Launch
// ---------------------------------------------------------------------------
extern "C" void kernel_launch(void* const* d_in, const int* in_sizes, int n_in,
                              void* d_out, int out_size)
{
    const float* x  = (const float*)d_in[0];
    const float* Wq = (const float*)d_in[1];
    const float* Wk = (const float*)d_in[2];
    const float* Wv = (const float*)d_in[3];
    const float* Wo = (const float*)d_in[4];
    const int* tokpos = (const int*)d_in[5];
    float* out = (float*)d_out;

    float *Qp, *Kp, *Vp, *Op;
    cudaGetSymbolAddress((void**)&Qp, g_Q);
    cudaGetSymbolAddress((void**)&Kp, g_K);
    cudaGetSymbolAddress((void**)&Vp, g_V);
    cudaGetSymbolAddress((void**)&Op, g_O);

    // Fused QKV projection: gridDim.z = 3
    dim3 qkv_grid(DMODEL / GBN, MROWS / GBM, 3);   // (8, 32, 3) = 768 blocks
    gemm_tf32_nt<<<qkv_grid, 256>>>(x, Wq, Qp, Wk, Kp, Wv, Vp,
                                    MROWS, DMODEL, DMODEL);

    // RoPE (table + fused Q/K apply)
    rope_table_kernel<<<(SEQ * HALF_DK + 255) / 256, 256>>>();
    int npairs = MROWS * (DMODEL / 2);
    dim3 rope_grid((npairs + 255) / 256, 2);
    rope_apply_kernel<<<rope_grid, 256>>>(Qp, Kp, tokpos);

    // Attention
    dim3 attn_grid(SEQ / BQ, BATCH * NHEADS);      // (16, 32)
    attn_kernel<<<attn_grid, 128>>>(Qp, Kp, Vp, Op);

    // Output projection
    dim3 o_grid(DMODEL / GBN, MROWS / GBM, 1);
    gemm_tf32_nt<<<o_grid, 256>>>(Op, Wo, out, nullptr, nullptr, nullptr, nullptr,
                                  MROWS, DMODEL, DMODEL);
}

// round 3
// speedup vs baseline: 5.0298x; 3.2676x over previous
#include <cuda_runtime.h>
#include <cuda_bf16.h>
#include <cuda_fp16.h>
#include <math.h>

// Problem constants
#define BATCH 2
#define SEQ 2048
#define DMODEL 1024
#define NHEADS 16
#define DK 64
#define MROWS (BATCH * SEQ)      // 4096
#define HALF_DK 32               // rope pairs per head
#define NEG_INF (-1e30f)

// ---------------------------------------------------------------------------
// Scratch buffers (allocation-free rule: __device__ globals)
// ---------------------------------------------------------------------------
__device__ float g_Q[MROWS * DMODEL];
__device__ float g_K[MROWS * DMODEL];
__device__ float g_V[MROWS * DMODEL];
__device__ float g_O[MROWS * DMODEL];
__device__ float g_cos[SEQ * HALF_DK];
__device__ float g_sin[SEQ * HALF_DK];
// fp16 attention operands, per-head layouts:
//   g_Qh, g_Kh: [B*H][S][DK]   (Q pre-scaled by 1/8)
//   g_VhT:      [B*H][DK][S]   (transposed for PV B-fragments)
__device__ __half g_Qh[BATCH * NHEADS * SEQ * DK];
__device__ __half g_Kh[BATCH * NHEADS * SEQ * DK];
__device__ __half g_VhT[BATCH * NHEADS * DK * SEQ];

// ---------------------------------------------------------------------------
// tf32 helpers
// ---------------------------------------------------------------------------
__device__ __forceinline__ unsigned f2tf32(float f) {
    unsigned u;
    asm("cvt.rna.tf32.f32 %0, %1;" : "=r"(u) : "f"(f));
    return u;
}

__device__ __forceinline__ void mma_tf32(
    float& c0, float& c1, float& c2, float& c3,
    unsigned a0, unsigned a1, unsigned a2, unsigned a3,
    unsigned b0, unsigned b1)
{
    asm volatile(
        "mma.sync.aligned.m16n8k8.row.col.f32.tf32.tf32.f32 "
        "{%0,%1,%2,%3}, {%4,%5,%6,%7}, {%8,%9}, {%0,%1,%2,%3};"
        : "+f"(c0), "+f"(c1), "+f"(c2), "+f"(c3)
        : "r"(a0), "r"(a1), "r"(a2), "r"(a3), "r"(b0), "r"(b1));
}

__device__ __forceinline__ void mma_f16(
    float* c, const unsigned* a, unsigned b0, unsigned b1)
{
    asm volatile(
        "mma.sync.aligned.m16n8k16.row.col.f32.f16.f16.f32 "
        "{%0,%1,%2,%3}, {%4,%5,%6,%7}, {%8,%9}, {%0,%1,%2,%3};"
        : "+f"(c[0]), "+f"(c[1]), "+f"(c[2]), "+f"(c[3])
        : "r"(a[0]), "r"(a[1]), "r"(a[2]), "r"(a[3]), "r"(b0), "r"(b1));
}

// ---------------------------------------------------------------------------
// tf32 GEMM NT: C[M,N] = A[M,K] * B[N,K]^T  (both row-major)
// 128x128 block tile, BK=32, 256 threads (8 warps), warp tile 64x32.
// gridDim.z selects among up to 3 (B, C) pairs for fused QKV.
// ---------------------------------------------------------------------------
#define GBM 128
#define GBN 128
#define GBK 32
#define GPAD 36

__global__ __launch_bounds__(256) void gemm_tf32_nt(
    const float* __restrict__ A,
    const float* __restrict__ B0, float* __restrict__ C0,
    const float* __restrict__ B1, float* __restrict__ C1,
    const float* __restrict__ B2, float* __restrict__ C2,
    int M, int N, int K)
{
    __shared__ unsigned As[GBM * GPAD];
    __shared__ unsigned Bs[GBN * GPAD];

    const float* B = B0; float* C = C0;
    if (blockIdx.z == 1) { B = B1; C = C1; }
    else if (blockIdx.z == 2) { B = B2; C = C2; }

    int tid = threadIdx.x;
    int warp = tid >> 5;
    int lane = tid & 31;
    int grp = lane >> 2;
    int tig = lane & 3;

    int wm = warp & 1;
    int wn = warp >> 1;

    int bx = blockIdx.x;
    int by = blockIdx.y;

    const float* Ablk = A + (size_t)by * GBM * K;
    const float* Bblk = B + (size_t)bx * GBN * K;

    int lr = tid >> 3;
    int lc = (tid & 7) * 4;

    float acc[4][4][4];
    #pragma unroll
    for (int i = 0; i < 4; i++)
        #pragma unroll
        for (int j = 0; j < 4; j++)
            #pragma unroll
            for (int f = 0; f < 4; f++) acc[i][j][f] = 0.f;

    for (int k0 = 0; k0 < K; k0 += GBK) {
        #pragma unroll
        for (int i = 0; i < 4; i++) {
            int row = lr + i * 32;
            float4 av = *(const float4*)(Ablk + (size_t)row * K + k0 + lc);
            float4 bv = *(const float4*)(Bblk + (size_t)row * K + k0 + lc);
            unsigned* ap = &As[row * GPAD + lc];
            unsigned* bp = &Bs[row * GPAD + lc];
            ap[0] = f2tf32(av.x); ap[1] = f2tf32(av.y);
            ap[2] = f2tf32(av.z); ap[3] = f2tf32(av.w);
            bp[0] = f2tf32(bv.x); bp[1] = f2tf32(bv.y);
            bp[2] = f2tf32(bv.z); bp[3] = f2tf32(bv.w);
        }
        __syncthreads();

        #pragma unroll
        for (int ks = 0; ks < GBK / 8; ks++) {
            int kk = ks * 8 + tig;
            unsigned af[4][4];
            #pragma unroll
            for (int mi = 0; mi < 4; mi++) {
                int m = wm * 64 + mi * 16 + grp;
                af[mi][0] = As[m * GPAD + kk];
                af[mi][1] = As[(m + 8) * GPAD + kk];
                af[mi][2] = As[m * GPAD + kk + 4];
                af[mi][3] = As[(m + 8) * GPAD + kk + 4];
            }
            unsigned bf[4][2];
            #pragma unroll
            for (int nj = 0; nj < 4; nj++) {
                int n = wn * 32 + nj * 8 + grp;
                bf[nj][0] = Bs[n * GPAD + kk];
                bf[nj][1] = Bs[n * GPAD + kk + 4];
            }
            #pragma unroll
            for (int mi = 0; mi < 4; mi++)
                #pragma unroll
                for (int nj = 0; nj < 4; nj++)
                    mma_tf32(acc[mi][nj][0], acc[mi][nj][1],
                             acc[mi][nj][2], acc[mi][nj][3],
                             af[mi][0], af[mi][1], af[mi][2], af[mi][3],
                             bf[nj][0], bf[nj][1]);
        }
        __syncthreads();
    }

    #pragma unroll
    for (int mi = 0; mi < 4; mi++) {
        int row0 = by * GBM + wm * 64 + mi * 16 + grp;
        #pragma unroll
        for (int nj = 0; nj < 4; nj++) {
            int col = bx * GBN + wn * 32 + nj * 8 + tig * 2;
            *(float2*)&C[(size_t)row0 * N + col] =
                make_float2(acc[mi][nj][0], acc[mi][nj][1]);
            *(float2*)&C[(size_t)(row0 + 8) * N + col] =
                make_float2(acc[mi][nj][2], acc[mi][nj][3]);
        }
    }
}

// ---------------------------------------------------------------------------
// RoPE cos/sin table
// ---------------------------------------------------------------------------
__global__ void rope_table_kernel()
{
    int idx = blockIdx.x * blockDim.x + threadIdx.x;
    if (idx >= SEQ * HALF_DK) return;
    int pos = idx >> 5;
    int i = idx & 31;
    double inv_d = exp(-((double)(2 * i) / 64.0) * log(10000.0));
    float inv_f = (float)inv_d;
    float arg_f = (float)pos * inv_f;
    double sv, cv;
    sincos((double)arg_f, &sv, &cv);
    g_cos[idx] = (float)cv;
    g_sin[idx] = (float)sv;
}

// ---------------------------------------------------------------------------
// RoPE + fp16 convert: read fp32 Q/K [row][h*64+d], apply rotation, write
// fp16 de-interleaved [b*16+h][s][64]. Q is additionally scaled by 1/8.
// blockIdx.y: 0 = Q, 1 = K.
// ---------------------------------------------------------------------------
__global__ __launch_bounds__(256) void rope_convert_kernel(
    const int* __restrict__ tokpos)
{
    int idx = blockIdx.x * blockDim.x + threadIdx.x;
    if (idx >= MROWS * (DMODEL / 2)) return;
    bool isK = blockIdx.y != 0;
    const float* X = isK ? g_K : g_Q;
    __half* Xh = isK ? g_Kh : g_Qh;

    int row = idx >> 9;          // 0..4095
    int cp = idx & 511;          // h*32 + i
    int h = cp >> 5;
    int i = cp & 31;
    int b = row >> 11;
    int s = row & 2047;
    int pos = tokpos[row];
    float c = g_cos[pos * HALF_DK + i];
    float sn = g_sin[pos * HALF_DK + i];
    float2 v = *(const float2*)&X[(size_t)row * DMODEL + cp * 2];
    float xe = v.x, xo = v.y;
    float r0 = xe * c - xo * sn;
    float r1 = xe * sn + xo * c;
    if (!isK) { r0 *= 0.125f; r1 *= 0.125f; }   // fold 1/sqrt(dk) into Q
    __half2 hv = __floats2half2_rn(r0, r1);
    *(__half2*)&Xh[(((size_t)(b * NHEADS + h) * SEQ + s)) * DK + 2 * i] = hv;
}

// ---------------------------------------------------------------------------
// V transpose-convert: fp32 [b*s][h*64+d] -> fp16 [b*16+h][d][s]
// One block per (64-row s-block, bh). 256 threads, smem staging.
// ---------------------------------------------------------------------------
__global__ __launch_bounds__(256) void v_convert_kernel()
{
    __shared__ float tile[64][65];
    int sb = blockIdx.x;     // s block (0..31)
    int bh = blockIdx.y;     // 0..31
    int b = bh >> 4, h = bh & 15;
    int tid = threadIdx.x;

    const float* src = g_V + ((size_t)(b * SEQ + sb * 64)) * DMODEL + h * DK;
    int r = tid >> 4;
    int c4 = (tid & 15) * 4;
    #pragma unroll
    for (int i = 0; i < 4; i++) {
        float4 v = *(const float4*)(src + (size_t)(r + i * 16) * DMODEL + c4);
        tile[r + i * 16][c4 + 0] = v.x;
        tile[r + i * 16][c4 + 1] = v.y;
        tile[r + i * 16][c4 + 2] = v.z;
        tile[r + i * 16][c4 + 3] = v.w;
    }
    __syncthreads();

    __half* dst = g_VhT + (size_t)bh * DK * SEQ + sb * 64;
    int d = tid & 63;
    int g = tid >> 6;       // 0..3
    #pragma unroll
    for (int j = 0; j < 2; j++) {
        int s0 = g * 16 + j * 8;
        __half hv[8];
        #pragma unroll
        for (int e = 0; e < 8; e++) hv[e] = __float2half(tile[s0 + e][d]);
        *(int4*)(dst + (size_t)d * SEQ + s0) = *(const int4*)hv;
    }
}

// ---------------------------------------------------------------------------
// FA2-style causal attention, fp16 mma (m16n8k16), fp32 accum.
// Block: 4 warps, Br=64 (16 rows/warp), Bc=64.
// grid: (SEQ/64, B*H); big q-tiles launched first (qt reversed).
// ---------------------------------------------------------------------------
__global__ __launch_bounds__(128) void attn_h_kernel(float* __restrict__ O)
{
    __shared__ __half Ksm[64][72];
    __shared__ __half Vsm[64][72];   // [d][k]

    int qt = gridDim.x - 1 - blockIdx.x;
    int bh = blockIdx.y;
    int tid = threadIdx.x;
    int warp = tid >> 5;
    int lane = tid & 31;
    int grp = lane >> 2;
    int tig = lane & 3;

    // Q fragments (16 rows x 64 cols per warp)
    unsigned aQ[4][4];
    {
        const __half* qbase = g_Qh + ((size_t)bh * SEQ + qt * 64 + warp * 16) * DK;
        #pragma unroll
        for (int kf = 0; kf < 4; kf++) {
            const __half* q0 = qbase + grp * DK + kf * 16 + 2 * tig;
            const __half* q1 = qbase + (grp + 8) * DK + kf * 16 + 2 * tig;
            aQ[kf][0] = *(const unsigned*)q0;
            aQ[kf][1] = *(const unsigned*)q1;
            aQ[kf][2] = *(const unsigned*)(q0 + 8);
            aQ[kf][3] = *(const unsigned*)(q1 + 8);
        }
    }

    float o[8][4];
    #pragma unroll
    for (int dj = 0; dj < 8; dj++)
        #pragma unroll
        for (int f = 0; f < 4; f++) o[dj][f] = 0.f;
    float m0 = NEG_INF, m1 = NEG_INF, l0 = 0.f, l1 = 0.f;

    const __half* kbase = g_Kh + (size_t)bh * SEQ * DK;
    const __half* vbase = g_VhT + (size_t)bh * DK * SEQ;

    for (int t = 0; t <= qt; t++) {
        // stage K tile [64][64] and V^T tile [64 d][64 k]
        const __half* kp = kbase + (size_t)t * 64 * DK;
        #pragma unroll
        for (int i = 0; i < 4; i++) {
            int idx = i * 128 + tid;     // 512 int4 total
            int r = idx >> 3;
            int c = (idx & 7) * 8;
            *(int4*)&Ksm[r][c] = *(const int4*)(kp + (size_t)r * DK + c);
            *(int4*)&Vsm[r][c] = *(const int4*)(vbase + (size_t)r * SEQ + t * 64 + c);
        }
        __syncthreads();

        // scores S = Q K^T (scale pre-folded into Q)
        float sc[8][4];
        #pragma unroll
        for (int nj = 0; nj < 8; nj++)
            #pragma unroll
            for (int f = 0; f < 4; f++) sc[nj][f] = 0.f;

        #pragma unroll
        for (int kf = 0; kf < 4; kf++) {
            #pragma unroll
            for (int nj = 0; nj < 8; nj++) {
                unsigned b0 = *(const unsigned*)&Ksm[nj * 8 + grp][kf * 16 + 2 * tig];
                unsigned b1 = *(const unsigned*)&Ksm[nj * 8 + grp][kf * 16 + 8 + 2 * tig];
                mma_f16(sc[nj], aQ[kf], b0, b1);
            }
        }

        // causal mask on diagonal tile
        if (t == qt) {
            int row0 = warp * 16 + grp;
            #pragma unroll
            for (int nj = 0; nj < 8; nj++) {
                int c0 = nj * 8 + 2 * tig;
                if (c0 > row0)         sc[nj][0] = NEG_INF;
                if (c0 + 1 > row0)     sc[nj][1] = NEG_INF;
                if (c0 > row0 + 8)     sc[nj][2] = NEG_INF;
                if (c0 + 1 > row0 + 8) sc[nj][3] = NEG_INF;
            }
        }

        // row max (2 rows per thread), reduce across quad
        float mx0 = m0, mx1 = m1;
        #pragma unroll
        for (int nj = 0; nj < 8; nj++) {
            mx0 = fmaxf(mx0, fmaxf(sc[nj][0], sc[nj][1]));
            mx1 = fmaxf(mx1, fmaxf(sc[nj][2], sc[nj][3]));
        }
        mx0 = fmaxf(mx0, __shfl_xor_sync(0xffffffffu, mx0, 1));
        mx0 = fmaxf(mx0, __shfl_xor_sync(0xffffffffu, mx0, 2));
        mx1 = fmaxf(mx1, __shfl_xor_sync(0xffffffffu, mx1, 1));
        mx1 = fmaxf(mx1, __shfl_xor_sync(0xffffffffu, mx1, 2));

        float corr0 = __expf(m0 - mx0);
        float corr1 = __expf(m1 - mx1);
        m0 = mx0; m1 = mx1;
        l0 *= corr0; l1 *= corr1;

        // exp + pack P fragments
        unsigned pf[4][4];
        #pragma unroll
        for (int nj = 0; nj < 8; nj++) {
            float p0 = __expf(sc[nj][0] - m0);
            float p1 = __expf(sc[nj][1] - m0);
            float p2 = __expf(sc[nj][2] - m1);
            float p3 = __expf(sc[nj][3] - m1);
            l0 += p0 + p1;
            l1 += p2 + p3;
            __half2 h01 = __floats2half2_rn(p0, p1);
            __half2 h23 = __floats2half2_rn(p2, p3);
            pf[nj >> 1][(nj & 1) * 2 + 0] = *(unsigned*)&h01;
            pf[nj >> 1][(nj & 1) * 2 + 1] = *(unsigned*)&h23;
        }

        // rescale O accumulators
        #pragma unroll
        for (int dj = 0; dj < 8; dj++) {
            o[dj][0] *= corr0; o[dj][1] *= corr0;
            o[dj][2] *= corr1; o[dj][3] *= corr1;
        }

        // O += P V
        #pragma unroll
        for (int kf = 0; kf < 4; kf++) {
            #pragma unroll
            for (int dj = 0; dj < 8; dj++) {
                unsigned b0 = *(const unsigned*)&Vsm[dj * 8 + grp][kf * 16 + 2 * tig];
                unsigned b1 = *(const unsigned*)&Vsm[dj * 8 + grp][kf * 16 + 8 + 2 * tig];
                mma_f16(o[dj], pf[kf], b0, b1);
            }
        }
        __syncthreads();
    }

    // finalize
    l0 += __shfl_xor_sync(0xffffffffu, l0, 1);
    l0 += __shfl_xor_sync(0xffffffffu, l0, 2);
    l1 += __shfl_xor_sync(0xffffffffu, l1, 1);
    l1 += __shfl_xor_sync(0xffffffffu, l1, 2);
    float il0 = 1.f / l0;
    float il1 = 1.f / l1;

    int b = bh >> 4, h = bh & 15;
    int srow = qt * 64 + warp * 16 + grp;
    float* op0 = O + ((size_t)(b * SEQ + srow)) * DMODEL + h * DK;
    float* op1 = op0 + (size_t)8 * DMODEL;
    #pragma unroll
    for (int dj = 0; dj < 8; dj++) {
        *(float2*)(op0 + dj * 8 + 2 * tig) =
            make_float2(o[dj][0] * il0, o[dj][1] * il0);
        *(float2*)(op1 + dj * 8 + 2 * tig) =
            make_float2(o[dj][2] * il1, o[dj][3] * il1);
    }
}

// ---------------------------------------------------------------------------
// Launch
// ---------------------------------------------------------------------------
extern "C" void kernel_launch(void* const* d_in, const int* in_sizes, int n_in,
                              void* d_out, int out_size)
{
    const float* x  = (const float*)d_in[0];
    const float* Wq = (const float*)d_in[1];
    const float* Wk = (const float*)d_in[2];
    const float* Wv = (const float*)d_in[3];
    const float* Wo = (const float*)d_in[4];
    const int* tokpos = (const int*)d_in[5];
    float* out = (float*)d_out;

    float *Qp, *Kp, *Vp, *Op;
    cudaGetSymbolAddress((void**)&Qp, g_Q);
    cudaGetSymbolAddress((void**)&Kp, g_K);
    cudaGetSymbolAddress((void**)&Vp, g_V);
    cudaGetSymbolAddress((void**)&Op, g_O);

    // Fused QKV projection
    dim3 qkv_grid(DMODEL / GBN, MROWS / GBM, 3);
    gemm_tf32_nt<<<qkv_grid, 256>>>(x, Wq, Qp, Wk, Kp, Wv, Vp,
                                    MROWS, DMODEL, DMODEL);

    // RoPE table + fused rope/convert for Q,K; V transpose-convert
    rope_table_kernel<<<(SEQ * HALF_DK + 255) / 256, 256>>>();
    int npairs = MROWS * (DMODEL / 2);
    dim3 rope_grid((npairs + 255) / 256, 2);
    rope_convert_kernel<<<rope_grid, 256>>>(tokpos);
    dim3 vconv_grid(SEQ / 64, BATCH * NHEADS);
    v_convert_kernel<<<vconv_grid, 256>>>();

    // Attention (tensor cores)
    dim3 attn_grid(SEQ / 64, BATCH * NHEADS);    // (32, 32)
    attn_h_kernel<<<attn_grid, 128>>>(Op);

    // Output projection
    dim3 o_grid(DMODEL / GBN, MROWS / GBM, 1);
    gemm_tf32_nt<<<o_grid, 256>>>(Op, Wo, out, nullptr, nullptr, nullptr, nullptr,
                                  MROWS, DMODEL, DMODEL);
}

// round 4
// speedup vs baseline: 7.0264x; 1.3970x over previous
#include <cuda_runtime.h>
#include <cuda_bf16.h>
#include <cuda_fp16.h>
#include <math.h>

// Problem constants
#define BATCH 2
#define SEQ 2048
#define DMODEL 1024
#define NHEADS 16
#define DK 64
#define MROWS (BATCH * SEQ)      // 4096
#define HALF_DK 32               // rope pairs per head
#define NEG_INF (-1e30f)

// ---------------------------------------------------------------------------
// Scratch buffers (allocation-free rule: __device__ globals)
// ---------------------------------------------------------------------------
__device__ float g_Q[MROWS * DMODEL];
__device__ float g_K[MROWS * DMODEL];
__device__ float g_V[MROWS * DMODEL];
__device__ float g_cos[SEQ * HALF_DK];
__device__ float g_sin[SEQ * HALF_DK];
// fp16 operands
__device__ __half g_xh[MROWS * DMODEL];         // x in fp16 (GEMM A)
__device__ __half g_Wqh[DMODEL * DMODEL];
__device__ __half g_Wkh[DMODEL * DMODEL];
__device__ __half g_Wvh[DMODEL * DMODEL];
__device__ __half g_Woh[DMODEL * DMODEL];
__device__ __half g_Oh[MROWS * DMODEL];         // attention output (GEMM A)
// fp16 attention operands, per-head layouts:
__device__ __half g_Qh[BATCH * NHEADS * SEQ * DK];   // [bh][s][d], pre-scaled 1/8
__device__ __half g_Kh[BATCH * NHEADS * SEQ * DK];   // [bh][s][d]
__device__ __half g_VhT[BATCH * NHEADS * DK * SEQ];  // [bh][d][s]

// ---------------------------------------------------------------------------
// helpers
// ---------------------------------------------------------------------------
__device__ __forceinline__ void mma_f16(
    float* c, const unsigned* a, unsigned b0, unsigned b1)
{
    asm volatile(
        "mma.sync.aligned.m16n8k16.row.col.f32.f16.f16.f32 "
        "{%0,%1,%2,%3}, {%4,%5,%6,%7}, {%8,%9}, {%0,%1,%2,%3};"
        : "+f"(c[0]), "+f"(c[1]), "+f"(c[2]), "+f"(c[3])
        : "r"(a[0]), "r"(a[1]), "r"(a[2]), "r"(a[3]), "r"(b0), "r"(b1));
}

__device__ __forceinline__ void cp_async16(unsigned smem_addr, const void* gptr)
{
    asm volatile("cp.async.cg.shared.global [%0], [%1], 16;"
                 :: "r"(smem_addr), "l"(gptr));
}

// ---------------------------------------------------------------------------
// fp32 -> fp16 convert, 8 elements/thread
// ---------------------------------------------------------------------------
__global__ __launch_bounds__(256) void convert_h_kernel(
    const float* __restrict__ src, __half* __restrict__ dst, int n)
{
    int i = (blockIdx.x * blockDim.x + threadIdx.x) * 8;
    if (i >= n) return;
    float4 a = *(const float4*)(src + i);
    float4 b = *(const float4*)(src + i + 4);
    __half h[8];
    h[0] = __float2half(a.x); h[1] = __float2half(a.y);
    h[2] = __float2half(a.z); h[3] = __float2half(a.w);
    h[4] = __float2half(b.x); h[5] = __float2half(b.y);
    h[6] = __float2half(b.z); h[7] = __float2half(b.w);
    *(int4*)(dst + i) = *(const int4*)h;
}

// ---------------------------------------------------------------------------
// fp16 GEMM NT: C[M,N](f32) = A[M,K](f16) * B[N,K](f16)^T
// 128x128 block tile, BK=32, 256 threads (8 warps), warp tile 64x32.
// cp.async double-buffered. Smem rows padded to 40 halfs (conflict-free).
// gridDim.z selects among up to 3 (B, C) pairs for fused QKV.
// ---------------------------------------------------------------------------
#define GBM 128
#define GBN 128
#define GBK 32
#define PADH 40

__global__ __launch_bounds__(256) void gemm_f16_nt(
    const __half* __restrict__ A,
    const __half* __restrict__ B0, float* __restrict__ C0,
    const __half* __restrict__ B1, float* __restrict__ C1,
    const __half* __restrict__ B2, float* __restrict__ C2,
    int M, int N, int K)
{
    __shared__ __half As[2][GBM * PADH];
    __shared__ __half Bs[2][GBN * PADH];

    const __half* B = B0; float* C = C0;
    if (blockIdx.z == 1) { B = B1; C = C1; }
    else if (blockIdx.z == 2) { B = B2; C = C2; }

    int tid = threadIdx.x;
    int warp = tid >> 5;
    int lane = tid & 31;
    int grp = lane >> 2;
    int tig = lane & 3;

    int wm = warp & 1;          // 64-row warp tile
    int wn = warp >> 1;         // 32-col warp tile

    const __half* Ablk = A + (size_t)blockIdx.y * GBM * K;
    const __half* Bblk = B + (size_t)blockIdx.x * GBN * K;

    unsigned asb = (unsigned)__cvta_generic_to_shared(&As[0][0]);
    unsigned bsb = (unsigned)__cvta_generic_to_shared(&Bs[0][0]);

    // cp.async mapping: 512 16B-chunks per matrix per tile, 2/thread
    int crow = tid >> 2;             // base row 0..63
    int cc8 = (tid & 3) * 8;         // col offset (halfs)

    float acc[4][4][4];
    #pragma unroll
    for (int i = 0; i < 4; i++)
        #pragma unroll
        for (int j = 0; j < 4; j++)
            #pragma unroll
            for (int f = 0; f < 4; f++) acc[i][j][f] = 0.f;

    const int NT = K / GBK;

    // prologue: load tile 0 into buf 0
    #pragma unroll
    for (int i = 0; i < 2; i++) {
        int row = crow + i * 64;
        unsigned so = (unsigned)((row * PADH + cc8) * 2);
        cp_async16(asb + so, Ablk + (size_t)row * K + cc8);
        cp_async16(bsb + so, Bblk + (size_t)row * K + cc8);
    }
    asm volatile("cp.async.commit_group;");

    int buf = 0;
    for (int kt = 0; kt < NT; kt++) {
        if (kt + 1 < NT) {
            int k0 = (kt + 1) * GBK;
            unsigned bufo = (unsigned)((buf ^ 1) * GBM * PADH * 2);
            #pragma unroll
            for (int i = 0; i < 2; i++) {
                int row = crow + i * 64;
                unsigned so = bufo + (unsigned)((row * PADH + cc8) * 2);
                cp_async16(asb + so, Ablk + (size_t)row * K + k0 + cc8);
                cp_async16(bsb + so, Bblk + (size_t)row * K + k0 + cc8);
            }
            asm volatile("cp.async.commit_group;");
            asm volatile("cp.async.wait_group 1;");
        } else {
            asm volatile("cp.async.wait_group 0;");
        }
        __syncthreads();

        const __half* Asm = &As[buf][0];
        const __half* Bsm = &Bs[buf][0];

        #pragma unroll
        for (int ks = 0; ks < 2; ks++) {
            int kk = ks * 16 + 2 * tig;
            unsigned af[4][4];
            #pragma unroll
            for (int mi = 0; mi < 4; mi++) {
                int m = wm * 64 + mi * 16 + grp;
                af[mi][0] = *(const unsigned*)&Asm[m * PADH + kk];
                af[mi][1] = *(const unsigned*)&Asm[(m + 8) * PADH + kk];
                af[mi][2] = *(const unsigned*)&Asm[m * PADH + kk + 8];
                af[mi][3] = *(const unsigned*)&Asm[(m + 8) * PADH + kk + 8];
            }
            unsigned bf[4][2];
            #pragma unroll
            for (int nj = 0; nj < 4; nj++) {
                int n = wn * 32 + nj * 8 + grp;
                bf[nj][0] = *(const unsigned*)&Bsm[n * PADH + kk];
                bf[nj][1] = *(const unsigned*)&Bsm[n * PADH + kk + 8];
            }
            #pragma unroll
            for (int mi = 0; mi < 4; mi++)
                #pragma unroll
                for (int nj = 0; nj < 4; nj++)
                    mma_f16(acc[mi][nj], af[mi], bf[nj][0], bf[nj][1]);
        }
        __syncthreads();
        buf ^= 1;
    }

    #pragma unroll
    for (int mi = 0; mi < 4; mi++) {
        int row0 = blockIdx.y * GBM + wm * 64 + mi * 16 + grp;
        #pragma unroll
        for (int nj = 0; nj < 4; nj++) {
            int col = blockIdx.x * GBN + wn * 32 + nj * 8 + tig * 2;
            *(float2*)&C[(size_t)row0 * N + col] =
                make_float2(acc[mi][nj][0], acc[mi][nj][1]);
            *(float2*)&C[(size_t)(row0 + 8) * N + col] =
                make_float2(acc[mi][nj][2], acc[mi][nj][3]);
        }
    }
}

// ---------------------------------------------------------------------------
// RoPE cos/sin table
// ---------------------------------------------------------------------------
__global__ void rope_table_kernel()
{
    int idx = blockIdx.x * blockDim.x + threadIdx.x;
    if (idx >= SEQ * HALF_DK) return;
    int pos = idx >> 5;
    int i = idx & 31;
    double inv_d = exp(-((double)(2 * i) / 64.0) * log(10000.0));
    float inv_f = (float)inv_d;
    float arg_f = (float)pos * inv_f;
    double sv, cv;
    sincos((double)arg_f, &sv, &cv);
    g_cos[idx] = (float)cv;
    g_sin[idx] = (float)sv;
}

// ---------------------------------------------------------------------------
// RoPE + fp16 convert: read fp32 Q/K, rotate, write fp16 per-head layout.
// Q additionally scaled by 1/8. blockIdx.y: 0 = Q, 1 = K.
// ---------------------------------------------------------------------------
__global__ __launch_bounds__(256) void rope_convert_kernel(
    const int* __restrict__ tokpos)
{
    int idx = blockIdx.x * blockDim.x + threadIdx.x;
    if (idx >= MROWS * (DMODEL / 2)) return;
    bool isK = blockIdx.y != 0;
    const float* X = isK ? g_K : g_Q;
    __half* Xh = isK ? g_Kh : g_Qh;

    int row = idx >> 9;
    int cp = idx & 511;
    int h = cp >> 5;
    int i = cp & 31;
    int b = row >> 11;
    int s = row & 2047;
    int pos = tokpos[row];
    float c = g_cos[pos * HALF_DK + i];
    float sn = g_sin[pos * HALF_DK + i];
    float2 v = *(const float2*)&X[(size_t)row * DMODEL + cp * 2];
    float xe = v.x, xo = v.y;
    float r0 = xe * c - xo * sn;
    float r1 = xe * sn + xo * c;
    if (!isK) { r0 *= 0.125f; r1 *= 0.125f; }
    __half2 hv = __floats2half2_rn(r0, r1);
    *(__half2*)&Xh[(((size_t)(b * NHEADS + h) * SEQ + s)) * DK + 2 * i] = hv;
}

// ---------------------------------------------------------------------------
// V transpose-convert: fp32 [b*s][h*64+d] -> fp16 [b*16+h][d][s]
// ---------------------------------------------------------------------------
__global__ __launch_bounds__(256) void v_convert_kernel()
{
    __shared__ float tile[64][65];
    int sb = blockIdx.x;
    int bh = blockIdx.y;
    int b = bh >> 4, h = bh & 15;
    int tid = threadIdx.x;

    const float* src = g_V + ((size_t)(b * SEQ + sb * 64)) * DMODEL + h * DK;
    int r = tid >> 4;
    int c4 = (tid & 15) * 4;
    #pragma unroll
    for (int i = 0; i < 4; i++) {
        float4 v = *(const float4*)(src + (size_t)(r + i * 16) * DMODEL + c4);
        tile[r + i * 16][c4 + 0] = v.x;
        tile[r + i * 16][c4 + 1] = v.y;
        tile[r + i * 16][c4 + 2] = v.z;
        tile[r + i * 16][c4 + 3] = v.w;
    }
    __syncthreads();

    __half* dst = g_VhT + (size_t)bh * DK * SEQ + sb * 64;
    int d = tid & 63;
    int g = tid >> 6;
    #pragma unroll
    for (int j = 0; j < 2; j++) {
        int s0 = g * 16 + j * 8;
        __half hv[8];
        #pragma unroll
        for (int e = 0; e < 8; e++) hv[e] = __float2half(tile[s0 + e][d]);
        *(int4*)(dst + (size_t)d * SEQ + s0) = *(const int4*)hv;
    }
}

// ---------------------------------------------------------------------------
// FA2-style causal attention, fp16 mma, fp32 accum.
// Block: 4 warps, Br=64, Bc=64. Writes fp16 O in [row][dmodel] layout.
// ---------------------------------------------------------------------------
__global__ __launch_bounds__(128) void attn_h_kernel()
{
    __shared__ __half Ksm[64][72];
    __shared__ __half Vsm[64][72];   // [d][k]

    int qt = gridDim.x - 1 - blockIdx.x;
    int bh = blockIdx.y;
    int tid = threadIdx.x;
    int warp = tid >> 5;
    int lane = tid & 31;
    int grp = lane >> 2;
    int tig = lane & 3;

    unsigned aQ[4][4];
    {
        const __half* qbase = g_Qh + ((size_t)bh * SEQ + qt * 64 + warp * 16) * DK;
        #pragma unroll
        for (int kf = 0; kf < 4; kf++) {
            const __half* q0 = qbase + grp * DK + kf * 16 + 2 * tig;
            const __half* q1 = qbase + (grp + 8) * DK + kf * 16 + 2 * tig;
            aQ[kf][0] = *(const unsigned*)q0;
            aQ[kf][1] = *(const unsigned*)q1;
            aQ[kf][2] = *(const unsigned*)(q0 + 8);
            aQ[kf][3] = *(const unsigned*)(q1 + 8);
        }
    }

    float o[8][4];
    #pragma unroll
    for (int dj = 0; dj < 8; dj++)
        #pragma unroll
        for (int f = 0; f < 4; f++) o[dj][f] = 0.f;
    float m0 = NEG_INF, m1 = NEG_INF, l0 = 0.f, l1 = 0.f;

    const __half* kbase = g_Kh + (size_t)bh * SEQ * DK;
    const __half* vbase = g_VhT + (size_t)bh * DK * SEQ;

    for (int t = 0; t <= qt; t++) {
        const __half* kp = kbase + (size_t)t * 64 * DK;
        #pragma unroll
        for (int i = 0; i < 4; i++) {
            int idx = i * 128 + tid;
            int r = idx >> 3;
            int c = (idx & 7) * 8;
            *(int4*)&Ksm[r][c] = *(const int4*)(kp + (size_t)r * DK + c);
            *(int4*)&Vsm[r][c] = *(const int4*)(vbase + (size_t)r * SEQ + t * 64 + c);
        }
        __syncthreads();

        float sc[8][4];
        #pragma unroll
        for (int nj = 0; nj < 8; nj++)
            #pragma unroll
            for (int f = 0; f < 4; f++) sc[nj][f] = 0.f;

        #pragma unroll
        for (int kf = 0; kf < 4; kf++) {
            #pragma unroll
            for (int nj = 0; nj < 8; nj++) {
                unsigned b0 = *(const unsigned*)&Ksm[nj * 8 + grp][kf * 16 + 2 * tig];
                unsigned b1 = *(const unsigned*)&Ksm[nj * 8 + grp][kf * 16 + 8 + 2 * tig];
                mma_f16(sc[nj], aQ[kf], b0, b1);
            }
        }

        if (t == qt) {
            int row0 = warp * 16 + grp;
            #pragma unroll
            for (int nj = 0; nj < 8; nj++) {
                int c0 = nj * 8 + 2 * tig;
                if (c0 > row0)         sc[nj][0] = NEG_INF;
                if (c0 + 1 > row0)     sc[nj][1] = NEG_INF;
                if (c0 > row0 + 8)     sc[nj][2] = NEG_INF;
                if (c0 + 1 > row0 + 8) sc[nj][3] = NEG_INF;
            }
        }

        float mx0 = m0, mx1 = m1;
        #pragma unroll
        for (int nj = 0; nj < 8; nj++) {
            mx0 = fmaxf(mx0, fmaxf(sc[nj][0], sc[nj][1]));
            mx1 = fmaxf(mx1, fmaxf(sc[nj][2], sc[nj][3]));
        }
        mx0 = fmaxf(mx0, __shfl_xor_sync(0xffffffffu, mx0, 1));
        mx0 = fmaxf(mx0, __shfl_xor_sync(0xffffffffu, mx0, 2));
        mx1 = fmaxf(mx1, __shfl_xor_sync(0xffffffffu, mx1, 1));
        mx1 = fmaxf(mx1, __shfl_xor_sync(0xffffffffu, mx1, 2));

        float corr0 = __expf(m0 - mx0);
        float corr1 = __expf(m1 - mx1);
        m0 = mx0; m1 = mx1;
        l0 *= corr0; l1 *= corr1;

        unsigned pf[4][4];
        #pragma unroll
        for (int nj = 0; nj < 8; nj++) {
            float p0 = __expf(sc[nj][0] - m0);
            float p1 = __expf(sc[nj][1] - m0);
            float p2 = __expf(sc[nj][2] - m1);
            float p3 = __expf(sc[nj][3] - m1);
            l0 += p0 + p1;
            l1 += p2 + p3;
            __half2 h01 = __floats2half2_rn(p0, p1);
            __half2 h23 = __floats2half2_rn(p2, p3);
            pf[nj >> 1][(nj & 1) * 2 + 0] = *(unsigned*)&h01;
            pf[nj >> 1][(nj & 1) * 2 + 1] = *(unsigned*)&h23;
        }

        #pragma unroll
        for (int dj = 0; dj < 8; dj++) {
            o[dj][0] *= corr0; o[dj][1] *= corr0;
            o[dj][2] *= corr1; o[dj][3] *= corr1;
        }

        #pragma unroll
        for (int kf = 0; kf < 4; kf++) {
            #pragma unroll
            for (int dj = 0; dj < 8; dj++) {
                unsigned b0 = *(const unsigned*)&Vsm[dj * 8 + grp][kf * 16 + 2 * tig];
                unsigned b1 = *(const unsigned*)&Vsm[dj * 8 + grp][kf * 16 + 8 + 2 * tig];
                mma_f16(o[dj], pf[kf], b0, b1);
            }
        }
        __syncthreads();
    }

    l0 += __shfl_xor_sync(0xffffffffu, l0, 1);
    l0 += __shfl_xor_sync(0xffffffffu, l0, 2);
    l1 += __shfl_xor_sync(0xffffffffu, l1, 1);
    l1 += __shfl_xor_sync(0xffffffffu, l1, 2);
    float il0 = 1.f / l0;
    float il1 = 1.f / l1;

    int b = bh >> 4, h = bh & 15;
    int srow = qt * 64 + warp * 16 + grp;
    __half* op0 = g_Oh + ((size_t)(b * SEQ + srow)) * DMODEL + h * DK;
    __half* op1 = op0 + (size_t)8 * DMODEL;
    #pragma unroll
    for (int dj = 0; dj < 8; dj++) {
        *(__half2*)(op0 + dj * 8 + 2 * tig) =
            __floats2half2_rn(o[dj][0] * il0, o[dj][1] * il0);
        *(__half2*)(op1 + dj * 8 + 2 * tig) =
            __floats2half2_rn(o[dj][2] * il1, o[dj][3] * il1);
    }
}

// ---------------------------------------------------------------------------
// Launch
// ---------------------------------------------------------------------------
extern "C" void kernel_launch(void* const* d_in, const int* in_sizes, int n_in,
                              void* d_out, int out_size)
{
    const float* x  = (const float*)d_in[0];
    const float* Wq = (const float*)d_in[1];
    const float* Wk = (const float*)d_in[2];
    const float* Wv = (const float*)d_in[3];
    const float* Wo = (const float*)d_in[4];
    const int* tokpos = (const int*)d_in[5];
    float* out = (float*)d_out;

    float *Qp, *Kp, *Vp;
    __half *xh, *Wqh, *Wkh, *Wvh, *Woh, *Oh;
    cudaGetSymbolAddress((void**)&Qp, g_Q);
    cudaGetSymbolAddress((void**)&Kp, g_K);
    cudaGetSymbolAddress((void**)&Vp, g_V);
    cudaGetSymbolAddress((void**)&xh, g_xh);
    cudaGetSymbolAddress((void**)&Wqh, g_Wqh);
    cudaGetSymbolAddress((void**)&Wkh, g_Wkh);
    cudaGetSymbolAddress((void**)&Wvh, g_Wvh);
    cudaGetSymbolAddress((void**)&Woh, g_Woh);
    cudaGetSymbolAddress((void**)&Oh, g_Oh);

    // fp16 conversions
    int nx = MROWS * DMODEL;        // 4M
    int nw = DMODEL * DMODEL;       // 1M
    convert_h_kernel<<<nx / (256 * 8), 256>>>(x, xh, nx);
    convert_h_kernel<<<nw / (256 * 8), 256>>>(Wq, Wqh, nw);
    convert_h_kernel<<<nw / (256 * 8), 256>>>(Wk, Wkh, nw);
    convert_h_kernel<<<nw / (256 * 8), 256>>>(Wv, Wvh, nw);
    convert_h_kernel<<<nw / (256 * 8), 256>>>(Wo, Woh, nw);

    // Fused QKV projection (fp16 tensor cores)
    dim3 qkv_grid(DMODEL / GBN, MROWS / GBM, 3);
    gemm_f16_nt<<<qkv_grid, 256>>>(xh, Wqh, Qp, Wkh, Kp, Wvh, Vp,
                                   MROWS, DMODEL, DMODEL);

    // RoPE table + rope/convert for Q,K; V transpose-convert
    rope_table_kernel<<<(SEQ * HALF_DK + 255) / 256, 256>>>();
    int npairs = MROWS * (DMODEL / 2);
    dim3 rope_grid((npairs + 255) / 256, 2);
    rope_convert_kernel<<<rope_grid, 256>>>(tokpos);
    dim3 vconv_grid(SEQ / 64, BATCH * NHEADS);
    v_convert_kernel<<<vconv_grid, 256>>>();

    // Attention (tensor cores), writes fp16 g_Oh
    dim3 attn_grid(SEQ / 64, BATCH * NHEADS);
    attn_h_kernel<<<attn_grid, 128>>>();

    // Output projection
    dim3 o_grid(DMODEL / GBN, MROWS / GBM, 1);
    gemm_f16_nt<<<o_grid, 256>>>(Oh, Woh, out, nullptr, nullptr, nullptr, nullptr,
                                 MROWS, DMODEL, DMODEL);
}

// round 5
// speedup vs baseline: 7.5975x; 1.0813x over previous
#include <cuda_runtime.h>
#include <cuda_bf16.h>
#include <cuda_fp16.h>
#include <math.h>

// Problem constants
#define BATCH 2
#define SEQ 2048
#define DMODEL 1024
#define NHEADS 16
#define DK 64
#define MROWS (BATCH * SEQ)      // 4096
#define HALF_DK 32
#define NEG_INF (-1e30f)

// ---------------------------------------------------------------------------
// Scratch buffers
// ---------------------------------------------------------------------------
__device__ float g_cos[SEQ * HALF_DK];
__device__ float g_sin[SEQ * HALF_DK];
__device__ __half g_xh[MROWS * DMODEL];
__device__ __half g_Wqh[DMODEL * DMODEL];
__device__ __half g_Wkh[DMODEL * DMODEL];
__device__ __half g_Wvh[DMODEL * DMODEL];
__device__ __half g_Woh[DMODEL * DMODEL];
__device__ __half g_Oh[MROWS * DMODEL];              // attention out (GEMM A)
// per-head attention operands, all [bh][s][d]:
__device__ __half g_Qh[BATCH * NHEADS * SEQ * DK];   // pre-scaled 1/8, rope'd
__device__ __half g_Kh[BATCH * NHEADS * SEQ * DK];   // rope'd
__device__ __half g_Vh[BATCH * NHEADS * SEQ * DK];

// ---------------------------------------------------------------------------
// helpers
// ---------------------------------------------------------------------------
__device__ __forceinline__ void mma_f16(
    float* c, const unsigned* a, unsigned b0, unsigned b1)
{
    asm volatile(
        "mma.sync.aligned.m16n8k16.row.col.f32.f16.f16.f32 "
        "{%0,%1,%2,%3}, {%4,%5,%6,%7}, {%8,%9}, {%0,%1,%2,%3};"
        : "+f"(c[0]), "+f"(c[1]), "+f"(c[2]), "+f"(c[3])
        : "r"(a[0]), "r"(a[1]), "r"(a[2]), "r"(a[3]), "r"(b0), "r"(b1));
}

__device__ __forceinline__ void cp_async16(unsigned smem_addr, const void* gptr)
{
    asm volatile("cp.async.cg.shared.global [%0], [%1], 16;"
                 :: "r"(smem_addr), "l"(gptr));
}

__device__ __forceinline__ void ldsm_x4(
    unsigned& r0, unsigned& r1, unsigned& r2, unsigned& r3, const void* p)
{
    unsigned addr = (unsigned)__cvta_generic_to_shared(p);
    asm volatile("ldmatrix.sync.aligned.m8n8.x4.shared.b16 {%0,%1,%2,%3}, [%4];"
                 : "=r"(r0), "=r"(r1), "=r"(r2), "=r"(r3) : "r"(addr));
}

__device__ __forceinline__ void ldsm_x4_trans(
    unsigned& r0, unsigned& r1, unsigned& r2, unsigned& r3, const void* p)
{
    unsigned addr = (unsigned)__cvta_generic_to_shared(p);
    asm volatile("ldmatrix.sync.aligned.m8n8.x4.trans.shared.b16 {%0,%1,%2,%3}, [%4];"
                 : "=r"(r0), "=r"(r1), "=r"(r2), "=r"(r3) : "r"(addr));
}

// ---------------------------------------------------------------------------
// Single fp32 -> fp16 convert for x + 4 weights. 8 elems/thread.
// idx < 4M -> x ; else weight (idx-4M)>>20, offset & (1M-1).
// ---------------------------------------------------------------------------
__global__ __launch_bounds__(256) void convert_all_kernel(
    const float* __restrict__ x,  const float* __restrict__ Wq,
    const float* __restrict__ Wk, const float* __restrict__ Wv,
    const float* __restrict__ Wo)
{
    size_t idx = ((size_t)blockIdx.x * blockDim.x + threadIdx.x) * 8;
    const float* src;
    __half* dst;
    size_t off;
    const size_t NX = (size_t)MROWS * DMODEL;      // 4M
    const size_t NW = (size_t)DMODEL * DMODEL;     // 1M
    if (idx < NX) { src = x; dst = g_xh; off = idx; }
    else {
        size_t r = idx - NX;
        int w = (int)(r >> 20);
        off = r & (NW - 1);
        switch (w) {
            case 0: src = Wq; dst = g_Wqh; break;
            case 1: src = Wk; dst = g_Wkh; break;
            case 2: src = Wv; dst = g_Wvh; break;
            default: src = Wo; dst = g_Woh; break;
        }
    }
    float4 a = *(const float4*)(src + off);
    float4 b = *(const float4*)(src + off + 4);
    __half h[8];
    h[0] = __float2half(a.x); h[1] = __float2half(a.y);
    h[2] = __float2half(a.z); h[3] = __float2half(a.w);
    h[4] = __float2half(b.x); h[5] = __float2half(b.y);
    h[6] = __float2half(b.z); h[7] = __float2half(b.w);
    *(int4*)(dst + off) = *(const int4*)h;
}

// ---------------------------------------------------------------------------
// RoPE cos/sin table
// ---------------------------------------------------------------------------
__global__ void rope_table_kernel()
{
    int idx = blockIdx.x * blockDim.x + threadIdx.x;
    if (idx >= SEQ * HALF_DK) return;
    int pos = idx >> 5;
    int i = idx & 31;
    double inv_d = exp(-((double)(2 * i) / 64.0) * log(10000.0));
    float inv_f = (float)inv_d;
    float arg_f = (float)pos * inv_f;
    double sv, cv;
    sincos((double)arg_f, &sv, &cv);
    g_cos[idx] = (float)cv;
    g_sin[idx] = (float)sv;
}

// ---------------------------------------------------------------------------
// fp16 GEMM NT, 128x128x32, 8 warps, cp.async double-buffered.
// fused=1: QKV projection. z=0 -> RoPE+0.125 -> g_Qh ; z=1 -> RoPE -> g_Kh ;
//          z=2 -> g_Vh. All per-head [bh][s][d] fp16.
// fused=0: plain fp32 C output (O projection).
// ---------------------------------------------------------------------------
#define GBM 128
#define GBN 128
#define GBK 32
#define PADH 40

__global__ __launch_bounds__(256) void gemm_f16_nt(
    const __half* __restrict__ A,
    const __half* __restrict__ B0, const __half* __restrict__ B1,
    const __half* __restrict__ B2,
    float* __restrict__ Cf, const int* __restrict__ tokpos,
    int fused, int M, int N, int K)
{
    __shared__ __half As[2][GBM * PADH];
    __shared__ __half Bs[2][GBN * PADH];

    const __half* B = B0;
    if (blockIdx.z == 1) B = B1;
    else if (blockIdx.z == 2) B = B2;

    int tid = threadIdx.x;
    int warp = tid >> 5;
    int lane = tid & 31;
    int grp = lane >> 2;
    int tig = lane & 3;
    int wm = warp & 1;
    int wn = warp >> 1;

    const __half* Ablk = A + (size_t)blockIdx.y * GBM * K;
    const __half* Bblk = B + (size_t)blockIdx.x * GBN * K;

    unsigned asb = (unsigned)__cvta_generic_to_shared(&As[0][0]);
    unsigned bsb = (unsigned)__cvta_generic_to_shared(&Bs[0][0]);

    int crow = tid >> 2;
    int cc8 = (tid & 3) * 8;

    float acc[4][4][4];
    #pragma unroll
    for (int i = 0; i < 4; i++)
        #pragma unroll
        for (int j = 0; j < 4; j++)
            #pragma unroll
            for (int f = 0; f < 4; f++) acc[i][j][f] = 0.f;

    const int NT = K / GBK;

    #pragma unroll
    for (int i = 0; i < 2; i++) {
        int row = crow + i * 64;
        unsigned so = (unsigned)((row * PADH + cc8) * 2);
        cp_async16(asb + so, Ablk + (size_t)row * K + cc8);
        cp_async16(bsb + so, Bblk + (size_t)row * K + cc8);
    }
    asm volatile("cp.async.commit_group;");

    int buf = 0;
    for (int kt = 0; kt < NT; kt++) {
        if (kt + 1 < NT) {
            int k0 = (kt + 1) * GBK;
            unsigned bufo = (unsigned)((buf ^ 1) * GBM * PADH * 2);
            #pragma unroll
            for (int i = 0; i < 2; i++) {
                int row = crow + i * 64;
                unsigned so = bufo + (unsigned)((row * PADH + cc8) * 2);
                cp_async16(asb + so, Ablk + (size_t)row * K + k0 + cc8);
                cp_async16(bsb + so, Bblk + (size_t)row * K + k0 + cc8);
            }
            asm volatile("cp.async.commit_group;");
            asm volatile("cp.async.wait_group 1;");
        } else {
            asm volatile("cp.async.wait_group 0;");
        }
        __syncthreads();

        const __half* Asm = &As[buf][0];
        const __half* Bsm = &Bs[buf][0];

        #pragma unroll
        for (int ks = 0; ks < 2; ks++) {
            int kk = ks * 16 + 2 * tig;
            unsigned af[4][4];
            #pragma unroll
            for (int mi = 0; mi < 4; mi++) {
                int m = wm * 64 + mi * 16 + grp;
                af[mi][0] = *(const unsigned*)&Asm[m * PADH + kk];
                af[mi][1] = *(const unsigned*)&Asm[(m + 8) * PADH + kk];
                af[mi][2] = *(const unsigned*)&Asm[m * PADH + kk + 8];
                af[mi][3] = *(const unsigned*)&Asm[(m + 8) * PADH + kk + 8];
            }
            unsigned bf[4][2];
            #pragma unroll
            for (int nj = 0; nj < 4; nj++) {
                int n = wn * 32 + nj * 8 + grp;
                bf[nj][0] = *(const unsigned*)&Bsm[n * PADH + kk];
                bf[nj][1] = *(const unsigned*)&Bsm[n * PADH + kk + 8];
            }
            #pragma unroll
            for (int mi = 0; mi < 4; mi++)
                #pragma unroll
                for (int nj = 0; nj < 4; nj++)
                    mma_f16(acc[mi][nj], af[mi], bf[nj][0], bf[nj][1]);
        }
        __syncthreads();
        buf ^= 1;
    }

    if (!fused) {
        #pragma unroll
        for (int mi = 0; mi < 4; mi++) {
            int row0 = blockIdx.y * GBM + wm * 64 + mi * 16 + grp;
            #pragma unroll
            for (int nj = 0; nj < 4; nj++) {
                int col = blockIdx.x * GBN + wn * 32 + nj * 8 + tig * 2;
                *(float2*)&Cf[(size_t)row0 * N + col] =
                    make_float2(acc[mi][nj][0], acc[mi][nj][1]);
                *(float2*)&Cf[(size_t)(row0 + 8) * N + col] =
                    make_float2(acc[mi][nj][2], acc[mi][nj][3]);
            }
        }
        return;
    }

    // fused epilogue: per-head fp16 layouts (+ RoPE for Q/K)
    int z = blockIdx.z;
    __half* dst = (z == 0) ? g_Qh : (z == 1) ? g_Kh : g_Vh;
    bool doRope = (z != 2);
    float qscale = (z == 0) ? 0.125f : 1.0f;

    #pragma unroll
    for (int mi = 0; mi < 4; mi++) {
        int row0 = blockIdx.y * GBM + wm * 64 + mi * 16 + grp;
        #pragma unroll
        for (int r2 = 0; r2 < 2; r2++) {
            int row = row0 + r2 * 8;
            int b = row >> 11;
            int s = row & 2047;
            int pos = doRope ? tokpos[row] : 0;
            #pragma unroll
            for (int nj = 0; nj < 4; nj++) {
                int col = blockIdx.x * GBN + wn * 32 + nj * 8 + tig * 2;
                int h = col >> 6;
                int dd = col & 63;
                float v0 = acc[mi][nj][r2 * 2 + 0];
                float v1 = acc[mi][nj][r2 * 2 + 1];
                if (doRope) {
                    int i = dd >> 1;
                    float c = g_cos[pos * HALF_DK + i];
                    float sn = g_sin[pos * HALF_DK + i];
                    float o0 = (v0 * c - v1 * sn) * qscale;
                    float o1 = (v0 * sn + v1 * c) * qscale;
                    v0 = o0; v1 = o1;
                }
                *(__half2*)&dst[((size_t)((b * NHEADS + h) * SEQ + s)) * DK + dd] =
                    __floats2half2_rn(v0, v1);
            }
        }
    }
}

// ---------------------------------------------------------------------------
// FA2-style causal attention, fp16 mma, fp32 accum, ldmatrix fragments.
// Block: 4 warps, Br=64, Bc=64. K and V staged in natural [s][d] layout;
// V B-fragments via ldmatrix.trans. Writes fp16 O [row][dmodel].
// ---------------------------------------------------------------------------
__global__ __launch_bounds__(128) void attn_h_kernel()
{
    __shared__ __half Ksm[64][72];
    __shared__ __half Vsm[64][72];

    int qt = gridDim.x - 1 - blockIdx.x;
    int bh = blockIdx.y;
    int tid = threadIdx.x;
    int warp = tid >> 5;
    int lane = tid & 31;
    int grp = lane >> 2;
    int tig = lane & 3;

    // ldmatrix lane addressing components
    int lm = lane >> 3;           // matrix id 0..3
    int l7 = lane & 7;

    unsigned aQ[4][4];
    {
        const __half* qbase = g_Qh + ((size_t)bh * SEQ + qt * 64 + warp * 16) * DK;
        #pragma unroll
        for (int kf = 0; kf < 4; kf++) {
            const __half* q0 = qbase + grp * DK + kf * 16 + 2 * tig;
            const __half* q1 = qbase + (grp + 8) * DK + kf * 16 + 2 * tig;
            aQ[kf][0] = *(const unsigned*)q0;
            aQ[kf][1] = *(const unsigned*)q1;
            aQ[kf][2] = *(const unsigned*)(q0 + 8);
            aQ[kf][3] = *(const unsigned*)(q1 + 8);
        }
    }

    float o[8][4];
    #pragma unroll
    for (int dj = 0; dj < 8; dj++)
        #pragma unroll
        for (int f = 0; f < 4; f++) o[dj][f] = 0.f;
    float m0 = NEG_INF, m1 = NEG_INF, l0 = 0.f, l1 = 0.f;

    const __half* kbase = g_Kh + (size_t)bh * SEQ * DK;
    const __half* vbase = g_Vh + (size_t)bh * SEQ * DK;

    for (int t = 0; t <= qt; t++) {
        const __half* kp = kbase + (size_t)t * 64 * DK;
        const __half* vp = vbase + (size_t)t * 64 * DK;
        #pragma unroll
        for (int i = 0; i < 4; i++) {
            int idx = i * 128 + tid;
            int r = idx >> 3;
            int c = (idx & 7) * 8;
            *(int4*)&Ksm[r][c] = *(const int4*)(kp + (size_t)r * DK + c);
            *(int4*)&Vsm[r][c] = *(const int4*)(vp + (size_t)r * DK + c);
        }
        __syncthreads();

        // S = Q K^T : B-fragments via non-trans ldmatrix over Ksm[n][k]
        float sc[8][4];
        #pragma unroll
        for (int nj = 0; nj < 8; nj++)
            #pragma unroll
            for (int f = 0; f < 4; f++) sc[nj][f] = 0.f;

        #pragma unroll
        for (int kf = 0; kf < 4; kf++) {
            #pragma unroll
            for (int njp = 0; njp < 4; njp++) {
                unsigned b0a, b1a, b0b, b1b;
                ldsm_x4(b0a, b1a, b0b, b1b,
                        &Ksm[njp * 16 + ((lm >> 1) << 3) + l7][kf * 16 + ((lm & 1) << 3)]);
                mma_f16(sc[2 * njp],     aQ[kf], b0a, b1a);
                mma_f16(sc[2 * njp + 1], aQ[kf], b0b, b1b);
            }
        }

        if (t == qt) {
            int row0 = warp * 16 + grp;
            #pragma unroll
            for (int nj = 0; nj < 8; nj++) {
                int c0 = nj * 8 + 2 * tig;
                if (c0 > row0)         sc[nj][0] = NEG_INF;
                if (c0 + 1 > row0)     sc[nj][1] = NEG_INF;
                if (c0 > row0 + 8)     sc[nj][2] = NEG_INF;
                if (c0 + 1 > row0 + 8) sc[nj][3] = NEG_INF;
            }
        }

        float mx0 = m0, mx1 = m1;
        #pragma unroll
        for (int nj = 0; nj < 8; nj++) {
            mx0 = fmaxf(mx0, fmaxf(sc[nj][0], sc[nj][1]));
            mx1 = fmaxf(mx1, fmaxf(sc[nj][2], sc[nj][3]));
        }
        mx0 = fmaxf(mx0, __shfl_xor_sync(0xffffffffu, mx0, 1));
        mx0 = fmaxf(mx0, __shfl_xor_sync(0xffffffffu, mx0, 2));
        mx1 = fmaxf(mx1, __shfl_xor_sync(0xffffffffu, mx1, 1));
        mx1 = fmaxf(mx1, __shfl_xor_sync(0xffffffffu, mx1, 2));

        float corr0 = __expf(m0 - mx0);
        float corr1 = __expf(m1 - mx1);
        m0 = mx0; m1 = mx1;
        l0 *= corr0; l1 *= corr1;

        unsigned pf[4][4];
        #pragma unroll
        for (int nj = 0; nj < 8; nj++) {
            float p0 = __expf(sc[nj][0] - m0);
            float p1 = __expf(sc[nj][1] - m0);
            float p2 = __expf(sc[nj][2] - m1);
            float p3 = __expf(sc[nj][3] - m1);
            l0 += p0 + p1;
            l1 += p2 + p3;
            __half2 h01 = __floats2half2_rn(p0, p1);
            __half2 h23 = __floats2half2_rn(p2, p3);
            pf[nj >> 1][(nj & 1) * 2 + 0] = *(unsigned*)&h01;
            pf[nj >> 1][(nj & 1) * 2 + 1] = *(unsigned*)&h23;
        }

        #pragma unroll
        for (int dj = 0; dj < 8; dj++) {
            o[dj][0] *= corr0; o[dj][1] *= corr0;
            o[dj][2] *= corr1; o[dj][3] *= corr1;
        }

        // O += P V : B-fragments via ldmatrix.trans over Vsm[k][n]
        #pragma unroll
        for (int kf = 0; kf < 4; kf++) {
            #pragma unroll
            for (int djp = 0; djp < 4; djp++) {
                unsigned b0a, b1a, b0b, b1b;
                ldsm_x4_trans(b0a, b1a, b0b, b1b,
                        &Vsm[kf * 16 + ((lm & 1) << 3) + l7][djp * 16 + ((lm >> 1) << 3)]);
                mma_f16(o[2 * djp],     pf[kf], b0a, b1a);
                mma_f16(o[2 * djp + 1], pf[kf], b0b, b1b);
            }
        }
        __syncthreads();
    }

    l0 += __shfl_xor_sync(0xffffffffu, l0, 1);
    l0 += __shfl_xor_sync(0xffffffffu, l0, 2);
    l1 += __shfl_xor_sync(0xffffffffu, l1, 1);
    l1 += __shfl_xor_sync(0xffffffffu, l1, 2);
    float il0 = 1.f / l0;
    float il1 = 1.f / l1;

    int b = bh >> 4, h = bh & 15;
    int srow = qt * 64 + warp * 16 + grp;
    __half* op0 = g_Oh + ((size_t)(b * SEQ + srow)) * DMODEL + h * DK;
    __half* op1 = op0 + (size_t)8 * DMODEL;
    #pragma unroll
    for (int dj = 0; dj < 8; dj++) {
        *(__half2*)(op0 + dj * 8 + 2 * tig) =
            __floats2half2_rn(o[dj][0] * il0, o[dj][1] * il0);
        *(__half2*)(op1 + dj * 8 + 2 * tig) =
            __floats2half2_rn(o[dj][2] * il1, o[dj][3] * il1);
    }
}

// ---------------------------------------------------------------------------
// Launch
// ---------------------------------------------------------------------------
extern "C" void kernel_launch(void* const* d_in, const int* in_sizes, int n_in,
                              void* d_out, int out_size)
{
    const float* x  = (const float*)d_in[0];
    const float* Wq = (const float*)d_in[1];
    const float* Wk = (const float*)d_in[2];
    const float* Wv = (const float*)d_in[3];
    const float* Wo = (const float*)d_in[4];
    const int* tokpos = (const int*)d_in[5];
    float* out = (float*)d_out;

    __half *xh, *Wqh, *Wkh, *Wvh, *Woh, *Oh;
    cudaGetSymbolAddress((void**)&xh, g_xh);
    cudaGetSymbolAddress((void**)&Wqh, g_Wqh);
    cudaGetSymbolAddress((void**)&Wkh, g_Wkh);
    cudaGetSymbolAddress((void**)&Wvh, g_Wvh);
    cudaGetSymbolAddress((void**)&Woh, g_Woh);
    cudaGetSymbolAddress((void**)&Oh, g_Oh);

    // RoPE table (needed by QKV GEMM epilogue)
    rope_table_kernel<<<(SEQ * HALF_DK + 255) / 256, 256>>>();

    // single fused fp16 conversion: x + 4 weights (8M elems, 8/thread)
    size_t ntot = (size_t)MROWS * DMODEL + 4 * (size_t)DMODEL * DMODEL;
    convert_all_kernel<<<(unsigned)(ntot / (256 * 8)), 256>>>(x, Wq, Wk, Wv, Wo);

    // Fused QKV projection + RoPE + per-head fp16 epilogue
    dim3 qkv_grid(DMODEL / GBN, MROWS / GBM, 3);
    gemm_f16_nt<<<qkv_grid, 256>>>(xh, Wqh, Wkh, Wvh,
                                   nullptr, tokpos, 1,
                                   MROWS, DMODEL, DMODEL);

    // Attention
    dim3 attn_grid(SEQ / 64, BATCH * NHEADS);
    attn_h_kernel<<<attn_grid, 128>>>();

    // Output projection (plain fp32 epilogue)
    dim3 o_grid(DMODEL / GBN, MROWS / GBM, 1);
    gemm_f16_nt<<<o_grid, 256>>>(Oh, Woh, nullptr, nullptr,
                                 out, tokpos, 0,
                                 MROWS, DMODEL, DMODEL);
}

// round 7
// speedup vs baseline: 7.7660x; 1.0222x over previous
#include <cuda_runtime.h>
#include <cuda_bf16.h>
#include <cuda_fp16.h>
#include <math.h>

// Problem constants
#define BATCH 2
#define SEQ 2048
#define DMODEL 1024
#define NHEADS 16
#define DK 64
#define MROWS (BATCH * SEQ)      // 4096
#define HALF_DK 32
#define NEG_INF (-1e30f)

// ---------------------------------------------------------------------------
// Scratch buffers
// ---------------------------------------------------------------------------
__device__ float g_cos[SEQ * HALF_DK];
__device__ float g_sin[SEQ * HALF_DK];
__device__ __half g_xh[MROWS * DMODEL];
__device__ __half g_Wqh[DMODEL * DMODEL];
__device__ __half g_Wkh[DMODEL * DMODEL];
__device__ __half g_Wvh[DMODEL * DMODEL];
__device__ __half g_Woh[DMODEL * DMODEL];
__device__ __half g_Oh[MROWS * DMODEL];              // attention out (GEMM A)
// per-head attention operands, all [bh][s][d]:
__device__ __half g_Qh[BATCH * NHEADS * SEQ * DK];   // pre-scaled 1/8, rope'd
__device__ __half g_Kh[BATCH * NHEADS * SEQ * DK];   // rope'd
__device__ __half g_Vh[BATCH * NHEADS * SEQ * DK];

// ---------------------------------------------------------------------------
// helpers
// ---------------------------------------------------------------------------
__device__ __forceinline__ void mma_f16(
    float* c, const unsigned* a, unsigned b0, unsigned b1)
{
    asm volatile(
        "mma.sync.aligned.m16n8k16.row.col.f32.f16.f16.f32 "
        "{%0,%1,%2,%3}, {%4,%5,%6,%7}, {%8,%9}, {%0,%1,%2,%3};"
        : "+f"(c[0]), "+f"(c[1]), "+f"(c[2]), "+f"(c[3])
        : "r"(a[0]), "r"(a[1]), "r"(a[2]), "r"(a[3]), "r"(b0), "r"(b1));
}

__device__ __forceinline__ void cp_async16(unsigned smem_addr, const void* gptr)
{
    asm volatile("cp.async.cg.shared.global [%0], [%1], 16;"
                 :: "r"(smem_addr), "l"(gptr));
}

__device__ __forceinline__ void ldsm_x4(
    unsigned& r0, unsigned& r1, unsigned& r2, unsigned& r3, const void* p)
{
    unsigned addr = (unsigned)__cvta_generic_to_shared(p);
    asm volatile("ldmatrix.sync.aligned.m8n8.x4.shared.b16 {%0,%1,%2,%3}, [%4];"
                 : "=r"(r0), "=r"(r1), "=r"(r2), "=r"(r3) : "r"(addr));
}

__device__ __forceinline__ void ldsm_x4_trans(
    unsigned& r0, unsigned& r1, unsigned& r2, unsigned& r3, const void* p)
{
    unsigned addr = (unsigned)__cvta_generic_to_shared(p);
    asm volatile("ldmatrix.sync.aligned.m8n8.x4.trans.shared.b16 {%0,%1,%2,%3}, [%4];"
                 : "=r"(r0), "=r"(r1), "=r"(r2), "=r"(r3) : "r"(addr));
}

// ---------------------------------------------------------------------------
// Single fp32 -> fp16 convert for x + 4 weights. 8 elems/thread.
// ---------------------------------------------------------------------------
__global__ __launch_bounds__(256) void convert_all_kernel(
    const float* __restrict__ x,  const float* __restrict__ Wq,
    const float* __restrict__ Wk, const float* __restrict__ Wv,
    const float* __restrict__ Wo)
{
    size_t idx = ((size_t)blockIdx.x * blockDim.x + threadIdx.x) * 8;
    const float* src;
    __half* dst;
    size_t off;
    const size_t NX = (size_t)MROWS * DMODEL;      // 4M
    const size_t NW = (size_t)DMODEL * DMODEL;     // 1M
    if (idx < NX) { src = x; dst = g_xh; off = idx; }
    else {
        size_t r = idx - NX;
        int w = (int)(r >> 20);
        off = r & (NW - 1);
        switch (w) {
            case 0: src = Wq; dst = g_Wqh; break;
            case 1: src = Wk; dst = g_Wkh; break;
            case 2: src = Wv; dst = g_Wvh; break;
            default: src = Wo; dst = g_Woh; break;
        }
    }
    float4 a = *(const float4*)(src + off);
    float4 b = *(const float4*)(src + off + 4);
    __half h[8];
    h[0] = __float2half(a.x); h[1] = __float2half(a.y);
    h[2] = __float2half(a.z); h[3] = __float2half(a.w);
    h[4] = __float2half(b.x); h[5] = __float2half(b.y);
    h[6] = __float2half(b.z); h[7] = __float2half(b.w);
    *(int4*)(dst + off) = *(const int4*)h;
}

// ---------------------------------------------------------------------------
// RoPE cos/sin table
// ---------------------------------------------------------------------------
__global__ void rope_table_kernel()
{
    int idx = blockIdx.x * blockDim.x + threadIdx.x;
    if (idx >= SEQ * HALF_DK) return;
    int pos = idx >> 5;
    int i = idx & 31;
    double inv_d = exp(-((double)(2 * i) / 64.0) * log(10000.0));
    float inv_f = (float)inv_d;
    float arg_f = (float)pos * inv_f;
    double sv, cv;
    sincos((double)arg_f, &sv, &cv);
    g_cos[idx] = (float)cv;
    g_sin[idx] = (float)sv;
}

// ---------------------------------------------------------------------------
// fp16 GEMM NT, 128x128x32, 8 warps, cp.async double-buffered.
// fused=1: QKV projection with RoPE epilogue. fused=0: fp32 C (O projection).
// ---------------------------------------------------------------------------
#define GBM 128
#define GBN 128
#define GBK 32
#define PADH 40

__global__ __launch_bounds__(256) void gemm_f16_nt(
    const __half* __restrict__ A,
    const __half* __restrict__ B0, const __half* __restrict__ B1,
    const __half* __restrict__ B2,
    float* __restrict__ Cf, const int* __restrict__ tokpos,
    int fused, int M, int N, int K)
{
    __shared__ __half As[2][GBM * PADH];
    __shared__ __half Bs[2][GBN * PADH];

    const __half* B = B0;
    if (blockIdx.z == 1) B = B1;
    else if (blockIdx.z == 2) B = B2;

    int tid = threadIdx.x;
    int warp = tid >> 5;
    int lane = tid & 31;
    int grp = lane >> 2;
    int tig = lane & 3;
    int wm = warp & 1;
    int wn = warp >> 1;

    const __half* Ablk = A + (size_t)blockIdx.y * GBM * K;
    const __half* Bblk = B + (size_t)blockIdx.x * GBN * K;

    unsigned asb = (unsigned)__cvta_generic_to_shared(&As[0][0]);
    unsigned bsb = (unsigned)__cvta_generic_to_shared(&Bs[0][0]);

    int crow = tid >> 2;
    int cc8 = (tid & 3) * 8;

    float acc[4][4][4];
    #pragma unroll
    for (int i = 0; i < 4; i++)
        #pragma unroll
        for (int j = 0; j < 4; j++)
            #pragma unroll
            for (int f = 0; f < 4; f++) acc[i][j][f] = 0.f;

    const int NT = K / GBK;

    #pragma unroll
    for (int i = 0; i < 2; i++) {
        int row = crow + i * 64;
        unsigned so = (unsigned)((row * PADH + cc8) * 2);
        cp_async16(asb + so, Ablk + (size_t)row * K + cc8);
        cp_async16(bsb + so, Bblk + (size_t)row * K + cc8);
    }
    asm volatile("cp.async.commit_group;");

    int buf = 0;
    for (int kt = 0; kt < NT; kt++) {
        if (kt + 1 < NT) {
            int k0 = (kt + 1) * GBK;
            unsigned bufo = (unsigned)((buf ^ 1) * GBM * PADH * 2);
            #pragma unroll
            for (int i = 0; i < 2; i++) {
                int row = crow + i * 64;
                unsigned so = bufo + (unsigned)((row * PADH + cc8) * 2);
                cp_async16(asb + so, Ablk + (size_t)row * K + k0 + cc8);
                cp_async16(bsb + so, Bblk + (size_t)row * K + k0 + cc8);
            }
            asm volatile("cp.async.commit_group;");
            asm volatile("cp.async.wait_group 1;");
        } else {
            asm volatile("cp.async.wait_group 0;");
        }
        __syncthreads();

        const __half* Asm = &As[buf][0];
        const __half* Bsm = &Bs[buf][0];

        #pragma unroll
        for (int ks = 0; ks < 2; ks++) {
            int kk = ks * 16 + 2 * tig;
            unsigned af[4][4];
            #pragma unroll
            for (int mi = 0; mi < 4; mi++) {
                int m = wm * 64 + mi * 16 + grp;
                af[mi][0] = *(const unsigned*)&Asm[m * PADH + kk];
                af[mi][1] = *(const unsigned*)&Asm[(m + 8) * PADH + kk];
                af[mi][2] = *(const unsigned*)&Asm[m * PADH + kk + 8];
                af[mi][3] = *(const unsigned*)&Asm[(m + 8) * PADH + kk + 8];
            }
            unsigned bf[4][2];
            #pragma unroll
            for (int nj = 0; nj < 4; nj++) {
                int n = wn * 32 + nj * 8 + grp;
                bf[nj][0] = *(const unsigned*)&Bsm[n * PADH + kk];
                bf[nj][1] = *(const unsigned*)&Bsm[n * PADH + kk + 8];
            }
            #pragma unroll
            for (int mi = 0; mi < 4; mi++)
                #pragma unroll
                for (int nj = 0; nj < 4; nj++)
                    mma_f16(acc[mi][nj], af[mi], bf[nj][0], bf[nj][1]);
        }
        __syncthreads();
        buf ^= 1;
    }

    if (!fused) {
        #pragma unroll
        for (int mi = 0; mi < 4; mi++) {
            int row0 = blockIdx.y * GBM + wm * 64 + mi * 16 + grp;
            #pragma unroll
            for (int nj = 0; nj < 4; nj++) {
                int col = blockIdx.x * GBN + wn * 32 + nj * 8 + tig * 2;
                *(float2*)&Cf[(size_t)row0 * N + col] =
                    make_float2(acc[mi][nj][0], acc[mi][nj][1]);
                *(float2*)&Cf[(size_t)(row0 + 8) * N + col] =
                    make_float2(acc[mi][nj][2], acc[mi][nj][3]);
            }
        }
        return;
    }

    // fused epilogue: per-head fp16 layouts (+ RoPE for Q/K)
    int z = blockIdx.z;
    __half* dst = (z == 0) ? g_Qh : (z == 1) ? g_Kh : g_Vh;
    bool doRope = (z != 2);
    float qscale = (z == 0) ? 0.125f : 1.0f;

    #pragma unroll
    for (int mi = 0; mi < 4; mi++) {
        int row0 = blockIdx.y * GBM + wm * 64 + mi * 16 + grp;
        #pragma unroll
        for (int r2 = 0; r2 < 2; r2++) {
            int row = row0 + r2 * 8;
            int b = row >> 11;
            int s = row & 2047;
            int pos = doRope ? tokpos[row] : 0;
            #pragma unroll
            for (int nj = 0; nj < 4; nj++) {
                int col = blockIdx.x * GBN + wn * 32 + nj * 8 + tig * 2;
                int h = col >> 6;
                int dd = col & 63;
                float v0 = acc[mi][nj][r2 * 2 + 0];
                float v1 = acc[mi][nj][r2 * 2 + 1];
                if (doRope) {
                    int i = dd >> 1;
                    float c = g_cos[pos * HALF_DK + i];
                    float sn = g_sin[pos * HALF_DK + i];
                    float o0 = (v0 * c - v1 * sn) * qscale;
                    float o1 = (v0 * sn + v1 * c) * qscale;
                    v0 = o0; v1 = o1;
                }
                *(__half2*)&dst[((size_t)((b * NHEADS + h) * SEQ + s)) * DK + dd] =
                    __floats2half2_rn(v0, v1);
            }
        }
    }
}

// ---------------------------------------------------------------------------
// FA2-style causal attention, fp16 mma, fp32 accum.
// 8 warps, Br=128 (16 rows/warp), Bc=64, cp.async double-buffered K/V tiles.
// grid: (SEQ/128, B*H), heaviest q-tiles first.
// ---------------------------------------------------------------------------
__global__ __launch_bounds__(256, 2) void attn_h_kernel()
{
    __shared__ __half Ksm[2][64][72];
    __shared__ __half Vsm[2][64][72];

    int qt = gridDim.x - 1 - blockIdx.x;
    int bh = blockIdx.y;
    int tid = threadIdx.x;
    int warp = tid >> 5;
    int lane = tid & 31;
    int grp = lane >> 2;
    int tig = lane & 3;
    int lm = lane >> 3;
    int l7 = lane & 7;

    // Q fragments: rows qt*128 + warp*16 .. +15
    unsigned aQ[4][4];
    {
        const __half* qbase = g_Qh + ((size_t)bh * SEQ + qt * 128 + warp * 16) * DK;
        #pragma unroll
        for (int kf = 0; kf < 4; kf++) {
            const __half* q0 = qbase + grp * DK + kf * 16 + 2 * tig;
            const __half* q1 = qbase + (grp + 8) * DK + kf * 16 + 2 * tig;
            aQ[kf][0] = *(const unsigned*)q0;
            aQ[kf][1] = *(const unsigned*)q1;
            aQ[kf][2] = *(const unsigned*)(q0 + 8);
            aQ[kf][3] = *(const unsigned*)(q1 + 8);
        }
    }

    float o[8][4];
    #pragma unroll
    for (int dj = 0; dj < 8; dj++)
        #pragma unroll
        for (int f = 0; f < 4; f++) o[dj][f] = 0.f;
    float m0 = NEG_INF, m1 = NEG_INF, l0 = 0.f, l1 = 0.f;

    const __half* kbase = g_Kh + (size_t)bh * SEQ * DK;
    const __half* vbase = g_Vh + (size_t)bh * SEQ * DK;

    unsigned ks_addr = (unsigned)__cvta_generic_to_shared(&Ksm[0][0][0]);
    unsigned vs_addr = (unsigned)__cvta_generic_to_shared(&Vsm[0][0][0]);
    const unsigned bufB = 64 * 72 * 2;     // bytes per buffer

    int nt = 2 * qt + 2;

    // stage tile 0 into buf 0: 512 16B-chunks per tensor, 2/thread
    {
        const __half* kp = kbase;
        const __half* vp = vbase;
        #pragma unroll
        for (int i = 0; i < 2; i++) {
            int id = i * 256 + tid;
            int r = id >> 3;
            int c8 = (id & 7) * 8;
            unsigned so = (unsigned)((r * 72 + c8) * 2);
            cp_async16(ks_addr + so, kp + (size_t)r * DK + c8);
            cp_async16(vs_addr + so, vp + (size_t)r * DK + c8);
        }
        asm volatile("cp.async.commit_group;");
    }

    int buf = 0;
    for (int t = 0; t < nt; t++) {
        if (t + 1 < nt) {
            const __half* kp = kbase + (size_t)(t + 1) * 64 * DK;
            const __half* vp = vbase + (size_t)(t + 1) * 64 * DK;
            unsigned bo = (buf ^ 1) * bufB;
            #pragma unroll
            for (int i = 0; i < 2; i++) {
                int id = i * 256 + tid;
                int r = id >> 3;
                int c8 = (id & 7) * 8;
                unsigned so = bo + (unsigned)((r * 72 + c8) * 2);
                cp_async16(ks_addr + so, kp + (size_t)r * DK + c8);
                cp_async16(vs_addr + so, vp + (size_t)r * DK + c8);
            }
            asm volatile("cp.async.commit_group;");
            asm volatile("cp.async.wait_group 1;");
        } else {
            asm volatile("cp.async.wait_group 0;");
        }
        __syncthreads();

        // S = Q K^T
        float sc[8][4];
        #pragma unroll
        for (int nj = 0; nj < 8; nj++)
            #pragma unroll
            for (int f = 0; f < 4; f++) sc[nj][f] = 0.f;

        #pragma unroll
        for (int kf = 0; kf < 4; kf++) {
            #pragma unroll
            for (int njp = 0; njp < 4; njp++) {
                unsigned b0a, b1a, b0b, b1b;
                ldsm_x4(b0a, b1a, b0b, b1b,
                        &Ksm[buf][njp * 16 + ((lm >> 1) << 3) + l7]
                            [kf * 16 + ((lm & 1) << 3)]);
                mma_f16(sc[2 * njp],     aQ[kf], b0a, b1a);
                mma_f16(sc[2 * njp + 1], aQ[kf], b0b, b1b);
            }
        }

        // causal mask (only possible on last two tiles)
        if (t >= 2 * qt) {
            int rowloc = warp * 16 + grp;
            int cb = (t - 2 * qt) * 64;
            #pragma unroll
            for (int nj = 0; nj < 8; nj++) {
                int c0 = cb + nj * 8 + 2 * tig;
                if (c0 > rowloc)         sc[nj][0] = NEG_INF;
                if (c0 + 1 > rowloc)     sc[nj][1] = NEG_INF;
                if (c0 > rowloc + 8)     sc[nj][2] = NEG_INF;
                if (c0 + 1 > rowloc + 8) sc[nj][3] = NEG_INF;
            }
        }

        float mx0 = m0, mx1 = m1;
        #pragma unroll
        for (int nj = 0; nj < 8; nj++) {
            mx0 = fmaxf(mx0, fmaxf(sc[nj][0], sc[nj][1]));
            mx1 = fmaxf(mx1, fmaxf(sc[nj][2], sc[nj][3]));
        }
        mx0 = fmaxf(mx0, __shfl_xor_sync(0xffffffffu, mx0, 1));
        mx0 = fmaxf(mx0, __shfl_xor_sync(0xffffffffu, mx0, 2));
        mx1 = fmaxf(mx1, __shfl_xor_sync(0xffffffffu, mx1, 1));
        mx1 = fmaxf(mx1, __shfl_xor_sync(0xffffffffu, mx1, 2));

        float corr0 = __expf(m0 - mx0);
        float corr1 = __expf(m1 - mx1);
        m0 = mx0; m1 = mx1;
        l0 *= corr0; l1 *= corr1;

        unsigned pf[4][4];
        #pragma unroll
        for (int nj = 0; nj < 8; nj++) {
            float p0 = __expf(sc[nj][0] - m0);
            float p1 = __expf(sc[nj][1] - m0);
            float p2 = __expf(sc[nj][2] - m1);
            float p3 = __expf(sc[nj][3] - m1);
            l0 += p0 + p1;
            l1 += p2 + p3;
            __half2 h01 = __floats2half2_rn(p0, p1);
            __half2 h23 = __floats2half2_rn(p2, p3);
            pf[nj >> 1][(nj & 1) * 2 + 0] = *(unsigned*)&h01;
            pf[nj >> 1][(nj & 1) * 2 + 1] = *(unsigned*)&h23;
        }

        #pragma unroll
        for (int dj = 0; dj < 8; dj++) {
            o[dj][0] *= corr0; o[dj][1] *= corr0;
            o[dj][2] *= corr1; o[dj][3] *= corr1;
        }

        // O += P V
        #pragma unroll
        for (int kf = 0; kf < 4; kf++) {
            #pragma unroll
            for (int djp = 0; djp < 4; djp++) {
                unsigned b0a, b1a, b0b, b1b;
                ldsm_x4_trans(b0a, b1a, b0b, b1b,
                        &Vsm[buf][kf * 16 + ((lm & 1) << 3) + l7]
                            [djp * 16 + ((lm >> 1) << 3)]);
                mma_f16(o[2 * djp],     pf[kf], b0a, b1a);
                mma_f16(o[2 * djp + 1], pf[kf], b0b, b1b);
            }
        }
        __syncthreads();
        buf ^= 1;
    }

    l0 += __shfl_xor_sync(0xffffffffu, l0, 1);
    l0 += __shfl_xor_sync(0xffffffffu, l0, 2);
    l1 += __shfl_xor_sync(0xffffffffu, l1, 1);
    l1 += __shfl_xor_sync(0xffffffffu, l1, 2);
    float il0 = 1.f / l0;
    float il1 = 1.f / l1;

    int b = bh >> 4, h = bh & 15;
    int srow = qt * 128 + warp * 16 + grp;
    __half* op0 = g_Oh + ((size_t)(b * SEQ + srow)) * DMODEL + h * DK;
    __half* op1 = op0 + (size_t)8 * DMODEL;
    #pragma unroll
    for (int dj = 0; dj < 8; dj++) {
        *(__half2*)(op0 + dj * 8 + 2 * tig) =
            __floats2half2_rn(o[dj][0] * il0, o[dj][1] * il0);
        *(__half2*)(op1 + dj * 8 + 2 * tig) =
            __floats2half2_rn(o[dj][2] * il1, o[dj][3] * il1);
    }
}

// ---------------------------------------------------------------------------
// Launch
// ---------------------------------------------------------------------------
extern "C" void kernel_launch(void* const* d_in, const int* in_sizes, int n_in,
                              void* d_out, int out_size)
{
    const float* x  = (const float*)d_in[0];
    const float* Wq = (const float*)d_in[1];
    const float* Wk = (const float*)d_in[2];
    const float* Wv = (const float*)d_in[3];
    const float* Wo = (const float*)d_in[4];
    const int* tokpos = (const int*)d_in[5];
    float* out = (float*)d_out;

    __half *xh, *Wqh, *Wkh, *Wvh, *Woh, *Oh;
    cudaGetSymbolAddress((void**)&xh, g_xh);
    cudaGetSymbolAddress((void**)&Wqh, g_Wqh);
    cudaGetSymbolAddress((void**)&Wkh, g_Wkh);
    cudaGetSymbolAddress((void**)&Wvh, g_Wvh);
    cudaGetSymbolAddress((void**)&Woh, g_Woh);
    cudaGetSymbolAddress((void**)&Oh, g_Oh);

    // RoPE table (needed by QKV GEMM epilogue)
    rope_table_kernel<<<(SEQ * HALF_DK + 255) / 256, 256>>>();

    // single fused fp16 conversion: x + 4 weights
    size_t ntot = (size_t)MROWS * DMODEL + 4 * (size_t)DMODEL * DMODEL;
    convert_all_kernel<<<(unsigned)(ntot / (256 * 8)), 256>>>(x, Wq, Wk, Wv, Wo);

    // Fused QKV projection + RoPE + per-head fp16 epilogue
    dim3 qkv_grid(DMODEL / GBN, MROWS / GBM, 3);
    gemm_f16_nt<<<qkv_grid, 256>>>(xh, Wqh, Wkh, Wvh,
                                   nullptr, tokpos, 1,
                                   MROWS, DMODEL, DMODEL);

    // Attention: Br=128, 8 warps, double-buffered
    dim3 attn_grid(SEQ / 128, BATCH * NHEADS);   // (16, 32)
    attn_h_kernel<<<attn_grid, 256>>>();

    // Output projection (plain fp32 epilogue)
    dim3 o_grid(DMODEL / GBN, MROWS / GBM, 1);
    gemm_f16_nt<<<o_grid, 256>>>(Oh, Woh, nullptr, nullptr,
                                 out, tokpos, 0,
                                 MROWS, DMODEL, DMODEL);
}